// round 2
// baseline (speedup 1.0000x reference)
#include <cuda_runtime.h>
#include <math.h>
#include <stdint.h>

#define INF_F (__int_as_float(0x7f800000))

// ---------------- problem constants ----------------
#define BQN 16
#define T0 1024
#define CD 256
#define ED 512
#define MAXROWS 131072   // Bq*Tq*k, identical for all 3 stages

// ---------------- static device scratch ----------------
__device__ float g_tokens_t[BQN*T0*CD];      // tokens_target (16MB)
__device__ float g_tokens_q[BQN*512*CD];
__device__ float g_skip    [BQN*512*CD];
__device__ float g_tq      [BQN*512*CD];
__device__ float g_tqbn    [BQN*512*CD];
__device__ float g_Qb      [BQN*512*CD];
__device__ float g_KV      [BQN*T0*2*CD];    // 33MB
__device__ float g_diff    [MAXROWS*CD];     // 134MB (also reused for sim)
__device__ float g_hidden  [MAXROWS*CD];     // 134MB
__device__ float g_mlph    [BQN*512*2*CD];
__device__ float g_centers_t[BQN*T0*3];
__device__ float g_centers_q[BQN*512*3];
__device__ int   g_rep[BQN*512];
__device__ int   g_nn [MAXROWS];
__device__ float g_psum[64*CD];
__device__ float g_psq [64*CD];
__device__ float g_stats[2*CD];
__device__ float g_pool[BQN*CD];
__device__ float g_embv[BQN*ED];

// ---------------- FPS ----------------
// one block per batch; 256 threads; sequential Tq steps
__global__ void fps_kernel(const float* __restrict__ centers, int Tt, int Tq,
                           int* __restrict__ rep_idx) {
    int b = blockIdx.x;
    const float* P = centers + (size_t)b * Tt * 3;
    __shared__ float sx[1024], sy[1024], sz[1024];
    __shared__ float s_bv[8];
    __shared__ int   s_bi[8];
    __shared__ int   s_cur;
    int tid = threadIdx.x;
    int npt = Tt >> 8;  // 4,2,1
    float d[4];
#pragma unroll
    for (int j = 0; j < 4; j++) d[j] = INF_F;
    for (int j = tid; j < Tt; j += 256) {
        sx[j] = P[j*3+0]; sy[j] = P[j*3+1]; sz[j] = P[j*3+2];
    }
    if (tid == 0) s_cur = 0;
    __syncthreads();

    for (int step = 0; step < Tq; step++) {
        int cur = s_cur;
        if (tid == 0) rep_idx[b*Tq + step] = cur;
        float cx = sx[cur], cy = sy[cur], cz = sz[cur];
        float bv = -INF_F; int bi = 0x7fffffff;
#pragma unroll
        for (int j = 0; j < 4; j++) {
            if (j < npt) {
                int p = j*256 + tid;
                float dx = sx[p]-cx, dy = sy[p]-cy, dz = sz[p]-cz;
                float dist = dx*dx + dy*dy + dz*dz;
                float dj = fminf(d[j], dist);
                d[j] = dj;
                // within-thread points are NOT globally ascending (strided),
                // so use full tie-break
                if (dj > bv || (dj == bv && p < bi)) { bv = dj; bi = p; }
            }
        }
#pragma unroll
        for (int off = 16; off > 0; off >>= 1) {
            float ov = __shfl_down_sync(0xffffffffu, bv, off);
            int   oi = __shfl_down_sync(0xffffffffu, bi, off);
            if (ov > bv || (ov == bv && oi < bi)) { bv = ov; bi = oi; }
        }
        if ((tid & 31) == 0) { s_bv[tid>>5] = bv; s_bi[tid>>5] = bi; }
        __syncthreads();
        if (tid == 0) {
            bv = s_bv[0]; bi = s_bi[0];
            for (int w = 1; w < 8; w++) {
                if (s_bv[w] > bv || (s_bv[w] == bv && s_bi[w] < bi)) { bv = s_bv[w]; bi = s_bi[w]; }
            }
            s_cur = bi;
        }
        __syncthreads();
    }
}

// ---------------- gather query rows ----------------
__global__ void gather_kernel(const float* __restrict__ tok_t,
                              const float* __restrict__ cent_t,
                              const int* __restrict__ rep,
                              float* __restrict__ tok_q,
                              float* __restrict__ skip,
                              float* __restrict__ cent_q,
                              int Tt, int Tq) {
    int p = blockIdx.x;            // b*Tq + q
    int b = p / Tq;
    int src = rep[p];
    int c = threadIdx.x;
    float v = tok_t[(size_t)(b*Tt + src)*CD + c];
    tok_q[(size_t)p*CD + c] = v;
    skip [(size_t)p*CD + c] = v;
    if (c < 3) cent_q[p*3 + c] = cent_t[(size_t)(b*Tt + src)*3 + c];
}

// ---------------- KNN ----------------
// one block per query; 256 threads; iterative k-argmin with tie->lowest index
__global__ void knn_kernel(const float* __restrict__ cent_q,
                           const float* __restrict__ cent_t,
                           int Tt, int Tq, int k, int* __restrict__ nn) {
    int p = blockIdx.x;
    int b = p / Tq;
    __shared__ float d2s[1024];
    __shared__ float s_bv[8];
    __shared__ int   s_bi[8];
    int tid = threadIdx.x;
    float qx = cent_q[p*3], qy = cent_q[p*3+1], qz = cent_q[p*3+2];
    float qq = qx*qx + qy*qy + qz*qz;
    const float* Pt = cent_t + (size_t)b*Tt*3;
    for (int t = tid; t < Tt; t += 256) {
        float tx = Pt[t*3], ty = Pt[t*3+1], tz = Pt[t*3+2];
        float tt = tx*tx + ty*ty + tz*tz;
        float dt = qx*tx + qy*ty + qz*tz;
        d2s[t] = (qq + tt) - 2.0f*dt;
    }
    __syncthreads();
    for (int sel = 0; sel < k; sel++) {
        float bv = INF_F; int bi = 0x7fffffff;
        for (int t = tid; t < Tt; t += 256) {
            float v = d2s[t];
            if (v < bv || (v == bv && t < bi)) { bv = v; bi = t; }
        }
#pragma unroll
        for (int off = 16; off > 0; off >>= 1) {
            float ov = __shfl_down_sync(0xffffffffu, bv, off);
            int   oi = __shfl_down_sync(0xffffffffu, bi, off);
            if (ov < bv || (ov == bv && oi < bi)) { bv = ov; bi = oi; }
        }
        if ((tid & 31) == 0) { s_bv[tid>>5] = bv; s_bi[tid>>5] = bi; }
        __syncthreads();
        if (tid == 0) {
            bv = s_bv[0]; bi = s_bi[0];
            for (int w = 1; w < 8; w++) {
                if (s_bv[w] < bv || (s_bv[w] == bv && s_bi[w] < bi)) { bv = s_bv[w]; bi = s_bi[w]; }
            }
            nn[p*k + sel] = bi;
            d2s[bi] = INF_F;
        }
        __syncthreads();
    }
}

// ---------------- BN stats (deterministic two-stage) ----------------
__global__ void bn_partial(const float* __restrict__ x1, int rows1,
                           const float* __restrict__ x2, int rows2,
                           float* __restrict__ psum, float* __restrict__ psq) {
    int c = threadIdx.x;   // 256 = CD
    int total = rows1 + rows2;
    float s = 0.f, sq = 0.f;
    for (int r = blockIdx.x; r < total; r += gridDim.x) {
        const float* row = (r < rows1) ? (x1 + (size_t)r*CD) : (x2 + (size_t)(r - rows1)*CD);
        float v = row[c];
        s += v; sq += v*v;
    }
    psum[blockIdx.x*CD + c] = s;
    psq [blockIdx.x*CD + c] = sq;
}

__global__ void bn_finalize(const float* __restrict__ psum, const float* __restrict__ psq,
                            int nb, int rows, float* __restrict__ stats) {
    int c = threadIdx.x;
    float s = 0.f, sq = 0.f;
    for (int b = 0; b < nb; b++) { s += psum[b*CD + c]; sq += psq[b*CD + c]; }
    float m = s / (float)rows;
    float v = sq / (float)rows - m*m;
    stats[c]      = m;
    stats[CD + c] = rsqrtf(v + 1e-5f);
}

__global__ void bn_apply(const float* __restrict__ in, float* __restrict__ out, int n,
                         const float* __restrict__ stats,
                         const float* __restrict__ gamma, const float* __restrict__ beta) {
    int i = blockIdx.x*blockDim.x + threadIdx.x;
    if (i >= n) return;
    int c = i & (CD-1);
    out[i] = (in[i] - stats[c]) * stats[CD + c] * gamma[c] + beta[c];
}

// ---------------- SGEMM 128x128x8, 256 thr, 8x8/thr ----------------
#define GBM 128
#define GBN 128
#define GBK 8
#define GTM 8
#define GTN 8

__global__ __launch_bounds__(256)
void sgemm_kernel(int M, int N, int K,
                  const float* __restrict__ A, const float* __restrict__ B,
                  const float* __restrict__ bias, const float* __restrict__ resid,
                  float* __restrict__ C, int relu) {
    __shared__ float As[GBK*GBM];
    __shared__ float Bs[GBK*GBN];
    int bx = blockIdx.x;   // N tile
    int by = blockIdx.y;   // M tile
    int tid = threadIdx.x;
    int tcol = tid & 15;   // 0..15
    int trow = tid >> 4;   // 0..15
    int aRow = tid >> 1;            // 0..127
    int aCol = (tid & 1) * 4;       // 0 or 4
    int bRow = tid >> 5;            // 0..7
    int bCol = (tid & 31) * 4;      // 0..124

    const float* Ab = A + (size_t)by*GBM*K;
    const float* Bb = B + bx*GBN;
    float acc[GTM][GTN];
#pragma unroll
    for (int i = 0; i < GTM; i++)
#pragma unroll
        for (int j = 0; j < GTN; j++) acc[i][j] = 0.f;

    for (int kt = 0; kt < K; kt += GBK) {
        float4 av = *(const float4*)(Ab + (size_t)aRow*K + kt + aCol);
        As[(aCol+0)*GBM + aRow] = av.x;
        As[(aCol+1)*GBM + aRow] = av.y;
        As[(aCol+2)*GBM + aRow] = av.z;
        As[(aCol+3)*GBM + aRow] = av.w;
        *(float4*)(Bs + bRow*GBN + bCol) = *(const float4*)(Bb + (size_t)(kt + bRow)*N + bCol);
        __syncthreads();
#pragma unroll
        for (int kk = 0; kk < GBK; kk++) {
            float4 a0 = *(const float4*)(&As[kk*GBM + trow*GTM]);
            float4 a1 = *(const float4*)(&As[kk*GBM + trow*GTM + 4]);
            float4 b0 = *(const float4*)(&Bs[kk*GBN + tcol*GTN]);
            float4 b1 = *(const float4*)(&Bs[kk*GBN + tcol*GTN + 4]);
            float ra[8] = {a0.x,a0.y,a0.z,a0.w,a1.x,a1.y,a1.z,a1.w};
            float rb[8] = {b0.x,b0.y,b0.z,b0.w,b1.x,b1.y,b1.z,b1.w};
#pragma unroll
            for (int i = 0; i < GTM; i++)
#pragma unroll
                for (int j = 0; j < GTN; j++) acc[i][j] += ra[i]*rb[j];
        }
        __syncthreads();
    }

#pragma unroll
    for (int i = 0; i < GTM; i++) {
        int row = by*GBM + trow*GTM + i;
#pragma unroll
        for (int j = 0; j < GTN; j += 4) {
            int col = bx*GBN + tcol*GTN + j;
            float4 v;
            v.x = acc[i][j+0]; v.y = acc[i][j+1]; v.z = acc[i][j+2]; v.w = acc[i][j+3];
            if (bias) { v.x += bias[col]; v.y += bias[col+1]; v.z += bias[col+2]; v.w += bias[col+3]; }
            if (resid) {
                float4 r = *(const float4*)(resid + (size_t)row*N + col);
                v.x += r.x; v.y += r.y; v.z += r.z; v.w += r.w;
            }
            if (relu) {
                v.x = fmaxf(v.x, 0.f); v.y = fmaxf(v.y, 0.f);
                v.z = fmaxf(v.z, 0.f); v.w = fmaxf(v.w, 0.f);
            }
            *(float4*)(C + (size_t)row*N + col) = v;
        }
    }
}

// ---------------- build diff rows: diff[p,n,c] = Q[p,c] - K[b,nn,c] ----------------
__global__ void build_diff(const float* __restrict__ Q, const float* __restrict__ KV,
                           const int* __restrict__ nn, float* __restrict__ diff,
                           int Tt, int Tq, int k) {
    int r = blockIdx.x;          // p*k + n
    int n = r % k;
    int p = r / k;
    int b = p / Tq;
    int idx = nn[p*k + n];
    int c = threadIdx.x;
    diff[(size_t)r*CD + c] = Q[(size_t)p*CD + c] - KV[(size_t)(b*Tt + idx)*2*CD + c];
}

// ---------------- softmax over k per (point,channel) + weighted V + skip ----------------
__global__ void attn_kernel(const float* __restrict__ sim, const float* __restrict__ KV,
                            const int* __restrict__ nn, const float* __restrict__ skip,
                            float* __restrict__ out, int Tt, int Tq, int k) {
    int p = blockIdx.x;
    int b = p / Tq;
    int c = threadIdx.x;
    __shared__ int nns[64];
    if (c < k) nns[c] = nn[p*k + c];
    __syncthreads();
    const float* S = sim + (size_t)p*k*CD;
    float m = -INF_F;
    for (int n = 0; n < k; n++) m = fmaxf(m, S[(size_t)n*CD + c]);
    float den = 0.f, acc = 0.f;
    for (int n = 0; n < k; n++) {
        float e = expf(S[(size_t)n*CD + c] - m);
        den += e;
        acc += e * KV[(size_t)(b*Tt + nns[n])*2*CD + CD + c];
    }
    out[(size_t)p*CD + c] = acc/den + skip[(size_t)p*CD + c];
}

// ---------------- final pooling / embedding ----------------
__global__ void pool_kernel(const float* __restrict__ tok, float* __restrict__ g, int Tq) {
    int b = blockIdx.x, c = threadIdx.x;
    float s = 0.f;
    for (int t = 0; t < Tq; t++) s += tok[(size_t)(b*Tq + t)*CD + c];
    g[b*CD + c] = s / (float)Tq;
}

__global__ void emb_kernel(const float* __restrict__ g, const float* __restrict__ W,
                           const float* __restrict__ bias, float* __restrict__ out) {
    int b = blockIdx.x, e = threadIdx.x;  // 512 threads
    __shared__ float gs[CD];
    if (e < CD) gs[e] = g[b*CD + e];
    __syncthreads();
    float s = 0.f;
    for (int c = 0; c < CD; c++) s += gs[c] * W[(size_t)c*ED + e];
    out[b*ED + e] = s + bias[e];
}

__global__ void final_bn_kernel(float* __restrict__ x, const float* __restrict__ gamma,
                                const float* __restrict__ beta) {
    int e = threadIdx.x;  // 512 threads, 1 block
    float s = 0.f;
    for (int b = 0; b < BQN; b++) s += x[b*ED + e];
    float m = s / (float)BQN;
    float v = 0.f;
    for (int b = 0; b < BQN; b++) { float d = x[b*ED + e] - m; v += d*d; }
    v /= (float)BQN;
    float rs = rsqrtf(v + 1e-5f);
    for (int b = 0; b < BQN; b++) {
        float val = (x[b*ED + e] - m) * rs * gamma[e] + beta[e];
        x[b*ED + e] = fmaxf(val, 0.f);
    }
}

__global__ void topk_norm_kernel(const float* __restrict__ x, float* __restrict__ out) {
    int b = blockIdx.x, t = threadIdx.x;  // 512 threads
    __shared__ float vals[ED], work[ED];
    __shared__ float red[16];
    __shared__ int   redi[16];
    __shared__ float s_thr, s_norm;
    float v = x[b*ED + t];
    vals[t] = v; work[t] = v;
    __syncthreads();
    for (int it = 0; it < 64; it++) {
        float bv = work[t]; int bi = t;
#pragma unroll
        for (int off = 16; off > 0; off >>= 1) {
            float ov = __shfl_down_sync(0xffffffffu, bv, off);
            int   oi = __shfl_down_sync(0xffffffffu, bi, off);
            if (ov > bv) { bv = ov; bi = oi; }
        }
        if ((t & 31) == 0) { red[t>>5] = bv; redi[t>>5] = bi; }
        __syncthreads();
        if (t == 0) {
            bv = red[0]; bi = redi[0];
            for (int w = 1; w < 16; w++) if (red[w] > bv) { bv = red[w]; bi = redi[w]; }
            work[bi] = -INF_F;
            if (it == 63) s_thr = bv;
        }
        __syncthreads();
    }
    float thr = s_thr;
    float kept = (vals[t] >= thr) ? vals[t] : 0.f;
    float sq = kept*kept;
#pragma unroll
    for (int off = 16; off > 0; off >>= 1) sq += __shfl_down_sync(0xffffffffu, sq, off);
    if ((t & 31) == 0) red[t>>5] = sq;
    __syncthreads();
    if (t == 0) {
        float s = 0.f;
        for (int w = 0; w < 16; w++) s += red[w];
        s_norm = fmaxf(sqrtf(s), 1e-12f);
    }
    __syncthreads();
    out[b*ED + t] = kept / s_norm;
}

// ---------------- host orchestration ----------------
extern "C" void kernel_launch(void* const* d_in, const int* in_sizes, int n_in,
                              void* d_out, int out_size) {
    const float* tokens = (const float*)d_in[0];
    const float* centers = (const float*)d_in[1];
    // d_in[2] = lrfs: provably unused by the output
    const float* wq     = (const float*)d_in[3];
    const float* wkv    = (const float*)d_in[4];
    const float* mlp_w1 = (const float*)d_in[5];
    const float* mlp_b1 = (const float*)d_in[6];
    const float* mlp_w2 = (const float*)d_in[7];
    const float* mlp_b2 = (const float*)d_in[8];
    const float* bn1_g  = (const float*)d_in[9];
    const float* bn1_b  = (const float*)d_in[10];
    const float* bn2_g  = (const float*)d_in[11];
    const float* bn2_b  = (const float*)d_in[12];
    const float* att_w1 = (const float*)d_in[13];
    const float* att_b1 = (const float*)d_in[14];
    const float* att_w2 = (const float*)d_in[15];
    const float* att_b2 = (const float*)d_in[16];
    const float* emb_w  = (const float*)d_in[17];
    const float* emb_b  = (const float*)d_in[18];
    const float* embn_g = (const float*)d_in[19];
    const float* embn_b = (const float*)d_in[20];

    float *tok_t, *tok_q, *skip, *tq, *tqbn, *Qb, *KV, *diffb, *hidb, *mlph;
    float *cent_t, *cent_q, *psum, *psq, *stats, *pool, *embv;
    int *rep, *nn;
    cudaGetSymbolAddress((void**)&tok_t,  g_tokens_t);
    cudaGetSymbolAddress((void**)&tok_q,  g_tokens_q);
    cudaGetSymbolAddress((void**)&skip,   g_skip);
    cudaGetSymbolAddress((void**)&tq,     g_tq);
    cudaGetSymbolAddress((void**)&tqbn,   g_tqbn);
    cudaGetSymbolAddress((void**)&Qb,     g_Qb);
    cudaGetSymbolAddress((void**)&KV,     g_KV);
    cudaGetSymbolAddress((void**)&diffb,  g_diff);
    cudaGetSymbolAddress((void**)&hidb,   g_hidden);
    cudaGetSymbolAddress((void**)&mlph,   g_mlph);
    cudaGetSymbolAddress((void**)&cent_t, g_centers_t);
    cudaGetSymbolAddress((void**)&cent_q, g_centers_q);
    cudaGetSymbolAddress((void**)&psum,   g_psum);
    cudaGetSymbolAddress((void**)&psq,    g_psq);
    cudaGetSymbolAddress((void**)&stats,  g_stats);
    cudaGetSymbolAddress((void**)&pool,   g_pool);
    cudaGetSymbolAddress((void**)&embv,   g_embv);
    cudaGetSymbolAddress((void**)&rep,    g_rep);
    cudaGetSymbolAddress((void**)&nn,     g_nn);

    cudaMemcpyAsync(tok_t,  tokens,  (size_t)BQN*T0*CD*sizeof(float), cudaMemcpyDeviceToDevice);
    cudaMemcpyAsync(cent_t, centers, (size_t)BQN*T0*3*sizeof(float),  cudaMemcpyDeviceToDevice);

    const int Tts[3] = {1024, 512, 256};
    const int Tqs[3] = {512, 256, 128};
    const int ks [3] = {16, 32, 64};

    for (int i = 0; i < 3; i++) {
        int Tt = Tts[i], Tq = Tqs[i], k = ks[i];
        int Mq = BQN*Tq, Mt = BQN*Tt, Mr = Mq*k;   // Mr == 131072

        fps_kernel   <<<BQN, 256>>>(cent_t, Tt, Tq, rep);
        gather_kernel<<<Mq, 256>>>(tok_t, cent_t, rep, tok_q, skip, cent_q, Tt, Tq);
        knn_kernel   <<<Mq, 256>>>(cent_q, cent_t, Tt, Tq, k, nn);

        if (i > 0) {
            bn_partial <<<64, 256>>>(tok_q, Mq, tok_t, Mt, psum, psq);
            bn_finalize<<<1, 256>>>(psum, psq, 64, Mq + Mt, stats);
            int nq = Mq*CD, nt = Mt*CD;
            bn_apply<<<(nq+255)/256, 256>>>(tok_q, tok_q, nq, stats, bn1_g + i*CD, bn1_b + i*CD);
            bn_apply<<<(nt+255)/256, 256>>>(tok_t, tok_t, nt, stats, bn1_g + i*CD, bn1_b + i*CD);
        }

        // Q = tok_q @ wq[i]
        sgemm_kernel<<<dim3(CD/GBN, Mq/GBM), 256>>>(Mq, CD, CD, tok_q, wq + (size_t)i*CD*CD,
                                                    nullptr, nullptr, Qb, 0);
        // KV = tok_t @ wkv[i]
        sgemm_kernel<<<dim3(2*CD/GBN, Mt/GBM), 256>>>(Mt, 2*CD, CD, tok_t, wkv + (size_t)i*CD*2*CD,
                                                      nullptr, nullptr, KV, 0);
        // diff rows
        build_diff<<<Mr, 256>>>(Qb, KV, nn, diffb, Tt, Tq, k);
        // hidden = relu(diff @ att_w1 + b1)
        sgemm_kernel<<<dim3(CD/GBN, Mr/GBM), 256>>>(Mr, CD, CD, diffb, att_w1 + (size_t)i*CD*CD,
                                                    att_b1 + i*CD, nullptr, hidb, 1);
        // sim = hidden @ att_w2 + b2   (reuse diff buffer)
        sgemm_kernel<<<dim3(CD/GBN, Mr/GBM), 256>>>(Mr, CD, CD, hidb, att_w2 + (size_t)i*CD*CD,
                                                    att_b2 + i*CD, nullptr, diffb, 0);
        // softmax over neighbors + weighted V + skip
        attn_kernel<<<Mq, 256>>>(diffb, KV, nn, skip, tq, Tt, Tq, k);

        // bn2 (out-of-place; tq is skip2)
        bn_partial <<<64, 256>>>(tq, Mq, nullptr, 0, psum, psq);
        bn_finalize<<<1, 256>>>(psum, psq, 64, Mq, stats);
        int n2 = Mq*CD;
        bn_apply<<<(n2+255)/256, 256>>>(tq, tqbn, n2, stats, bn2_g + i*CD, bn2_b + i*CD);

        // mlp
        sgemm_kernel<<<dim3(2*CD/GBN, Mq/GBM), 256>>>(Mq, 2*CD, CD, tqbn, mlp_w1 + (size_t)i*CD*2*CD,
                                                      mlp_b1 + i*2*CD, nullptr, mlph, 1);
        sgemm_kernel<<<dim3(CD/GBN, Mq/GBM), 256>>>(Mq, CD, 2*CD, mlph, mlp_w2 + (size_t)i*2*CD*CD,
                                                    mlp_b2 + i*CD, tq /*resid*/, tok_t, 0);

        cudaMemcpyAsync(cent_t, cent_q, (size_t)Mq*3*sizeof(float), cudaMemcpyDeviceToDevice);
    }

    pool_kernel     <<<BQN, 256>>>(tok_t, pool, 128);
    emb_kernel      <<<BQN, 512>>>(pool, emb_w, emb_b, embv);
    final_bn_kernel <<<1, 512>>>(embv, embn_g, embn_b);
    topk_norm_kernel<<<BQN, 512>>>(embv, (float*)d_out);
}

// round 3
// speedup vs baseline: 2.0545x; 2.0545x over previous
#include <cuda_runtime.h>
#include <math.h>
#include <stdint.h>

#define INF_F (__int_as_float(0x7f800000))

// ---------------- problem constants ----------------
#define BQN 16
#define T0 1024
#define CD 256
#define ED 512
#define MAXROWS 131072   // Bq*Tq*k, identical for all 3 stages

// ---------------- static device scratch ----------------
__device__ float g_tokens_t[BQN*T0*CD];      // stage outputs (16MB)
__device__ float g_tokens_q[BQN*512*CD];
__device__ float g_skip    [BQN*512*CD];
__device__ float g_tq      [BQN*512*CD];
__device__ float g_tqbn    [BQN*512*CD];
__device__ float g_Qb      [BQN*512*CD];
__device__ float g_KV      [BQN*T0*2*CD];    // 33MB
__device__ float g_hidden  [MAXROWS*CD];     // 134MB
__device__ float g_sim     [MAXROWS*CD];     // 134MB
__device__ float g_mlph    [BQN*512*2*CD];
__device__ float g_centers_a[BQN*T0*3];
__device__ float g_centers_b[BQN*512*3];
__device__ int   g_rep[BQN*512];
__device__ int   g_nn [MAXROWS];
__device__ float g_psum[64*CD];
__device__ float g_psq [64*CD];
__device__ float g_stats[2*CD];
__device__ float g_pool[BQN*CD];
__device__ float g_embv[BQN*ED];

// ---------------- FPS ----------------
__global__ void fps_kernel(const float* __restrict__ centers, int Tt, int Tq,
                           int* __restrict__ rep_idx) {
    int b = blockIdx.x;
    const float* P = centers + (size_t)b * Tt * 3;
    __shared__ float sx[1024], sy[1024], sz[1024];
    __shared__ float s_bv[8];
    __shared__ int   s_bi[8];
    __shared__ int   s_cur;
    int tid = threadIdx.x;
    int npt = Tt >> 8;  // 4,2,1
    float d[4];
#pragma unroll
    for (int j = 0; j < 4; j++) d[j] = INF_F;
    for (int j = tid; j < Tt; j += 256) {
        sx[j] = P[j*3+0]; sy[j] = P[j*3+1]; sz[j] = P[j*3+2];
    }
    if (tid == 0) s_cur = 0;
    __syncthreads();

    for (int step = 0; step < Tq; step++) {
        int cur = s_cur;
        if (tid == 0) rep_idx[b*Tq + step] = cur;
        float cx = sx[cur], cy = sy[cur], cz = sz[cur];
        float bv = -INF_F; int bi = 0x7fffffff;
#pragma unroll
        for (int j = 0; j < 4; j++) {
            if (j < npt) {
                int p = j*256 + tid;
                float dx = sx[p]-cx, dy = sy[p]-cy, dz = sz[p]-cz;
                float dist = dx*dx + dy*dy + dz*dz;
                float dj = fminf(d[j], dist);
                d[j] = dj;
                if (dj > bv || (dj == bv && p < bi)) { bv = dj; bi = p; }
            }
        }
#pragma unroll
        for (int off = 16; off > 0; off >>= 1) {
            float ov = __shfl_down_sync(0xffffffffu, bv, off);
            int   oi = __shfl_down_sync(0xffffffffu, bi, off);
            if (ov > bv || (ov == bv && oi < bi)) { bv = ov; bi = oi; }
        }
        if ((tid & 31) == 0) { s_bv[tid>>5] = bv; s_bi[tid>>5] = bi; }
        __syncthreads();
        if (tid == 0) {
            bv = s_bv[0]; bi = s_bi[0];
            for (int w = 1; w < 8; w++) {
                if (s_bv[w] > bv || (s_bv[w] == bv && s_bi[w] < bi)) { bv = s_bv[w]; bi = s_bi[w]; }
            }
            s_cur = bi;
        }
        __syncthreads();
    }
}

// ---------------- gather query rows ----------------
__global__ void gather_kernel(const float* __restrict__ tok_t,
                              const float* __restrict__ cent_t,
                              const int* __restrict__ rep,
                              float* __restrict__ tok_q,
                              float* __restrict__ skip,
                              float* __restrict__ cent_q,
                              int Tt, int Tq) {
    int p = blockIdx.x;            // b*Tq + q
    int b = p / Tq;
    int src = rep[p];
    int c = threadIdx.x;
    float v = tok_t[(size_t)(b*Tt + src)*CD + c];
    tok_q[(size_t)p*CD + c] = v;
    skip [(size_t)p*CD + c] = v;
    if (c < 3) cent_q[p*3 + c] = cent_t[(size_t)(b*Tt + src)*3 + c];
}

// ---------------- KNN ----------------
__global__ void knn_kernel(const float* __restrict__ cent_q,
                           const float* __restrict__ cent_t,
                           int Tt, int Tq, int k, int* __restrict__ nn) {
    int p = blockIdx.x;
    int b = p / Tq;
    __shared__ float d2s[1024];
    __shared__ float s_bv[8];
    __shared__ int   s_bi[8];
    int tid = threadIdx.x;
    float qx = cent_q[p*3], qy = cent_q[p*3+1], qz = cent_q[p*3+2];
    float qq = qx*qx + qy*qy + qz*qz;
    const float* Pt = cent_t + (size_t)b*Tt*3;
    for (int t = tid; t < Tt; t += 256) {
        float tx = Pt[t*3], ty = Pt[t*3+1], tz = Pt[t*3+2];
        float tt = tx*tx + ty*ty + tz*tz;
        float dt = qx*tx + qy*ty + qz*tz;
        d2s[t] = (qq + tt) - 2.0f*dt;
    }
    __syncthreads();
    for (int sel = 0; sel < k; sel++) {
        float bv = INF_F; int bi = 0x7fffffff;
        for (int t = tid; t < Tt; t += 256) {
            float v = d2s[t];
            if (v < bv || (v == bv && t < bi)) { bv = v; bi = t; }
        }
#pragma unroll
        for (int off = 16; off > 0; off >>= 1) {
            float ov = __shfl_down_sync(0xffffffffu, bv, off);
            int   oi = __shfl_down_sync(0xffffffffu, bi, off);
            if (ov < bv || (ov == bv && oi < bi)) { bv = ov; bi = oi; }
        }
        if ((tid & 31) == 0) { s_bv[tid>>5] = bv; s_bi[tid>>5] = bi; }
        __syncthreads();
        if (tid == 0) {
            bv = s_bv[0]; bi = s_bi[0];
            for (int w = 1; w < 8; w++) {
                if (s_bv[w] < bv || (s_bv[w] == bv && s_bi[w] < bi)) { bv = s_bv[w]; bi = s_bi[w]; }
            }
            nn[p*k + sel] = bi;
            d2s[bi] = INF_F;
        }
        __syncthreads();
    }
}

// ---------------- BN stats (deterministic two-stage) ----------------
__global__ void bn_partial(const float* __restrict__ x1, int rows1,
                           const float* __restrict__ x2, int rows2,
                           float* __restrict__ psum, float* __restrict__ psq) {
    int c = threadIdx.x;   // 256 = CD
    int total = rows1 + rows2;
    float s = 0.f, sq = 0.f;
    for (int r = blockIdx.x; r < total; r += gridDim.x) {
        const float* row = (r < rows1) ? (x1 + (size_t)r*CD) : (x2 + (size_t)(r - rows1)*CD);
        float v = row[c];
        s += v; sq += v*v;
    }
    psum[blockIdx.x*CD + c] = s;
    psq [blockIdx.x*CD + c] = sq;
}

__global__ void bn_finalize(const float* __restrict__ psum, const float* __restrict__ psq,
                            int nb, int rows, float* __restrict__ stats) {
    int c = threadIdx.x;
    float s = 0.f, sq = 0.f;
    for (int b = 0; b < nb; b++) { s += psum[b*CD + c]; sq += psq[b*CD + c]; }
    float m = s / (float)rows;
    float v = sq / (float)rows - m*m;
    stats[c]      = m;
    stats[CD + c] = rsqrtf(v + 1e-5f);
}

__global__ void bn_apply(const float* __restrict__ in, float* __restrict__ out, int n,
                         const float* __restrict__ stats,
                         const float* __restrict__ gamma, const float* __restrict__ beta) {
    int i = blockIdx.x*blockDim.x + threadIdx.x;
    if (i >= n) return;
    int c = i & (CD-1);
    out[i] = (in[i] - stats[c]) * stats[CD + c] * gamma[c] + beta[c];
}

// ---------------- TF32 tensor-core GEMM ----------------
// C[M,N] = A[M,K] @ B[K,N] (+bias)(+resid)(relu)
// BM=128, BN=128, BK=32, 256 threads (8 warps, 2x4), warp tile 64x32,
// mma.m16n8k8.tf32. DIFF mode builds A rows on the fly: A[r] = Q[r/k] - KV[nn[r]].
#define TBM 128
#define TBN 128
#define TBK 32
#define AS_STRIDE 36
#define BS_STRIDE 136

__device__ __forceinline__ uint32_t f2tf32(float x) {
    uint32_t r;
    asm("cvt.rna.tf32.f32 %0, %1;" : "=r"(r) : "f"(x));
    return r;
}

__device__ __forceinline__ void mma_tf32(float* c, const uint32_t* a, const uint32_t* b) {
    asm volatile(
        "mma.sync.aligned.m16n8k8.row.col.f32.tf32.tf32.f32 "
        "{%0,%1,%2,%3}, {%4,%5,%6,%7}, {%8,%9}, {%0,%1,%2,%3};\n"
        : "+f"(c[0]), "+f"(c[1]), "+f"(c[2]), "+f"(c[3])
        : "r"(a[0]), "r"(a[1]), "r"(a[2]), "r"(a[3]),
          "r"(b[0]), "r"(b[1]));
}

template<bool DIFF>
__global__ __launch_bounds__(256)
void tf32gemm(int M, int N, int K,
              const float* __restrict__ A,
              const float* __restrict__ Q, const float* __restrict__ KV,
              const int* __restrict__ nn, int Tq, int knn_k, int Tt,
              const float* __restrict__ B,
              const float* __restrict__ bias, const float* __restrict__ resid,
              float* __restrict__ C, int relu) {
    __shared__ uint32_t As[TBM*AS_STRIDE];
    __shared__ uint32_t Bs[TBK*BS_STRIDE];
    __shared__ int sQoff[TBM];
    __shared__ int sKoff[TBM];

    int tid = threadIdx.x;
    int lane = tid & 31;
    int warp = tid >> 5;
    int wm = warp >> 2;          // 0..1
    int wn = warp & 3;           // 0..3
    int bx = blockIdx.x;         // N tile
    int by = blockIdx.y;         // M tile
    int row0 = by*TBM;
    int col0 = bx*TBN;

    if (DIFF) {
        if (tid < TBM) {
            int r = row0 + tid;
            int p = r / knn_k;
            int b = p / Tq;
            sQoff[tid] = p * CD;
            sKoff[tid] = (b*Tt + nn[r]) * (2*CD);
        }
        __syncthreads();
    }

    float acc[4][4][4];
#pragma unroll
    for (int i = 0; i < 4; i++)
#pragma unroll
        for (int j = 0; j < 4; j++)
#pragma unroll
            for (int r = 0; r < 4; r++) acc[i][j][r] = 0.f;

    int ldrow = tid >> 3;        // 0..31
    int ldcol = (tid & 7) * 4;   // 0,4,...,28

    for (int kt = 0; kt < K; kt += TBK) {
        // stage A: 128x32
#pragma unroll
        for (int i = 0; i < 4; i++) {
            int arow = ldrow + 32*i;
            float4 v;
            if (DIFF) {
                const float4 q  = *(const float4*)(Q  + sQoff[arow] + kt + ldcol);
                const float4 kv = *(const float4*)(KV + sKoff[arow] + kt + ldcol);
                v.x = q.x - kv.x; v.y = q.y - kv.y; v.z = q.z - kv.z; v.w = q.w - kv.w;
            } else {
                v = *(const float4*)(A + (size_t)(row0 + arow)*K + kt + ldcol);
            }
            uint32_t* dst = &As[arow*AS_STRIDE + ldcol];
            dst[0] = f2tf32(v.x); dst[1] = f2tf32(v.y);
            dst[2] = f2tf32(v.z); dst[3] = f2tf32(v.w);
        }
        // stage B: 32x128
#pragma unroll
        for (int i = 0; i < 4; i++) {
            int bcol = ldcol + 32*i;
            float4 v = *(const float4*)(B + (size_t)(kt + ldrow)*N + col0 + bcol);
            uint32_t* dst = &Bs[ldrow*BS_STRIDE + bcol];
            dst[0] = f2tf32(v.x); dst[1] = f2tf32(v.y);
            dst[2] = f2tf32(v.z); dst[3] = f2tf32(v.w);
        }
        __syncthreads();

#pragma unroll
        for (int kk = 0; kk < 4; kk++) {
            int kc = kk*8;
            uint32_t a[4][4];
#pragma unroll
            for (int mf = 0; mf < 4; mf++) {
                int r1 = wm*64 + mf*16 + (lane>>2);
                a[mf][0] = As[r1*AS_STRIDE      + kc     + (lane&3)];
                a[mf][1] = As[(r1+8)*AS_STRIDE  + kc     + (lane&3)];
                a[mf][2] = As[r1*AS_STRIDE      + kc + 4 + (lane&3)];
                a[mf][3] = As[(r1+8)*AS_STRIDE  + kc + 4 + (lane&3)];
            }
            uint32_t b[4][2];
#pragma unroll
            for (int nf = 0; nf < 4; nf++) {
                int ncol = wn*32 + nf*8 + (lane>>2);
                b[nf][0] = Bs[(kc     + (lane&3))*BS_STRIDE + ncol];
                b[nf][1] = Bs[(kc + 4 + (lane&3))*BS_STRIDE + ncol];
            }
#pragma unroll
            for (int mf = 0; mf < 4; mf++)
#pragma unroll
                for (int nf = 0; nf < 4; nf++)
                    mma_tf32(acc[mf][nf], a[mf], b[nf]);
        }
        __syncthreads();
    }

    // epilogue
#pragma unroll
    for (int mf = 0; mf < 4; mf++) {
#pragma unroll
        for (int nf = 0; nf < 4; nf++) {
            int r = row0 + wm*64 + mf*16 + (lane>>2);
            int c = col0 + wn*32 + nf*8 + (lane&3)*2;
#pragma unroll
            for (int half = 0; half < 2; half++) {
                int rr = r + half*8;
                float v0 = acc[mf][nf][half*2+0];
                float v1 = acc[mf][nf][half*2+1];
                if (bias)  { v0 += bias[c]; v1 += bias[c+1]; }
                if (resid) {
                    const float2 rv = *(const float2*)(resid + (size_t)rr*N + c);
                    v0 += rv.x; v1 += rv.y;
                }
                if (relu) { v0 = fmaxf(v0, 0.f); v1 = fmaxf(v1, 0.f); }
                float2 out; out.x = v0; out.y = v1;
                *(float2*)(C + (size_t)rr*N + c) = out;
            }
        }
    }
}

// ---------------- softmax over k per (point,channel) + weighted V + skip ----------------
__global__ void attn_kernel(const float* __restrict__ sim, const float* __restrict__ KV,
                            const int* __restrict__ nn, const float* __restrict__ skip,
                            float* __restrict__ out, int Tt, int Tq, int k) {
    int p = blockIdx.x;
    int b = p / Tq;
    int c = threadIdx.x;
    __shared__ int nns[64];
    if (c < k) nns[c] = nn[p*k + c];
    __syncthreads();
    const float* S = sim + (size_t)p*k*CD;
    float m = -INF_F;
    for (int n = 0; n < k; n++) m = fmaxf(m, S[(size_t)n*CD + c]);
    float den = 0.f, acc = 0.f;
    for (int n = 0; n < k; n++) {
        float e = expf(S[(size_t)n*CD + c] - m);
        den += e;
        acc += e * KV[(size_t)(b*Tt + nns[n])*2*CD + CD + c];
    }
    out[(size_t)p*CD + c] = acc/den + skip[(size_t)p*CD + c];
}

// ---------------- final pooling / embedding ----------------
__global__ void pool_kernel(const float* __restrict__ tok, float* __restrict__ g, int Tq) {
    int b = blockIdx.x, c = threadIdx.x;
    float s = 0.f;
    for (int t = 0; t < Tq; t++) s += tok[(size_t)(b*Tq + t)*CD + c];
    g[b*CD + c] = s / (float)Tq;
}

__global__ void emb_kernel(const float* __restrict__ g, const float* __restrict__ W,
                           const float* __restrict__ bias, float* __restrict__ out) {
    int b = blockIdx.x, e = threadIdx.x;  // 512 threads
    __shared__ float gs[CD];
    if (e < CD) gs[e] = g[b*CD + e];
    __syncthreads();
    float s = 0.f;
    for (int c = 0; c < CD; c++) s += gs[c] * W[(size_t)c*ED + e];
    out[b*ED + e] = s + bias[e];
}

__global__ void final_bn_kernel(float* __restrict__ x, const float* __restrict__ gamma,
                                const float* __restrict__ beta) {
    int e = threadIdx.x;  // 512 threads, 1 block
    float s = 0.f;
    for (int b = 0; b < BQN; b++) s += x[b*ED + e];
    float m = s / (float)BQN;
    float v = 0.f;
    for (int b = 0; b < BQN; b++) { float d = x[b*ED + e] - m; v += d*d; }
    v /= (float)BQN;
    float rs = rsqrtf(v + 1e-5f);
    for (int b = 0; b < BQN; b++) {
        float val = (x[b*ED + e] - m) * rs * gamma[e] + beta[e];
        x[b*ED + e] = fmaxf(val, 0.f);
    }
}

__global__ void topk_norm_kernel(const float* __restrict__ x, float* __restrict__ out) {
    int b = blockIdx.x, t = threadIdx.x;  // 512 threads
    __shared__ float vals[ED], work[ED];
    __shared__ float red[16];
    __shared__ int   redi[16];
    __shared__ float s_thr, s_norm;
    float v = x[b*ED + t];
    vals[t] = v; work[t] = v;
    __syncthreads();
    for (int it = 0; it < 64; it++) {
        float bv = work[t]; int bi = t;
#pragma unroll
        for (int off = 16; off > 0; off >>= 1) {
            float ov = __shfl_down_sync(0xffffffffu, bv, off);
            int   oi = __shfl_down_sync(0xffffffffu, bi, off);
            if (ov > bv) { bv = ov; bi = oi; }
        }
        if ((t & 31) == 0) { red[t>>5] = bv; redi[t>>5] = bi; }
        __syncthreads();
        if (t == 0) {
            bv = red[0]; bi = redi[0];
            for (int w = 1; w < 16; w++) if (red[w] > bv) { bv = red[w]; bi = redi[w]; }
            work[bi] = -INF_F;
            if (it == 63) s_thr = bv;
        }
        __syncthreads();
    }
    float thr = s_thr;
    float kept = (vals[t] >= thr) ? vals[t] : 0.f;
    float sq = kept*kept;
#pragma unroll
    for (int off = 16; off > 0; off >>= 1) sq += __shfl_down_sync(0xffffffffu, sq, off);
    if ((t & 31) == 0) red[t>>5] = sq;
    __syncthreads();
    if (t == 0) {
        float s = 0.f;
        for (int w = 0; w < 16; w++) s += red[w];
        s_norm = fmaxf(sqrtf(s), 1e-12f);
    }
    __syncthreads();
    out[b*ED + t] = kept / s_norm;
}

// ---------------- host orchestration ----------------
extern "C" void kernel_launch(void* const* d_in, const int* in_sizes, int n_in,
                              void* d_out, int out_size) {
    const float* tokens = (const float*)d_in[0];
    const float* centers = (const float*)d_in[1];
    // d_in[2] = lrfs: unused by the output
    const float* wq     = (const float*)d_in[3];
    const float* wkv    = (const float*)d_in[4];
    const float* mlp_w1 = (const float*)d_in[5];
    const float* mlp_b1 = (const float*)d_in[6];
    const float* mlp_w2 = (const float*)d_in[7];
    const float* mlp_b2 = (const float*)d_in[8];
    const float* bn1_g  = (const float*)d_in[9];
    const float* bn1_b  = (const float*)d_in[10];
    const float* bn2_g  = (const float*)d_in[11];
    const float* bn2_b  = (const float*)d_in[12];
    const float* att_w1 = (const float*)d_in[13];
    const float* att_b1 = (const float*)d_in[14];
    const float* att_w2 = (const float*)d_in[15];
    const float* att_b2 = (const float*)d_in[16];
    const float* emb_w  = (const float*)d_in[17];
    const float* emb_b  = (const float*)d_in[18];
    const float* embn_g = (const float*)d_in[19];
    const float* embn_b = (const float*)d_in[20];

    float *tok_buf, *tok_q, *skip, *tq, *tqbn, *Qb, *KV, *hidb, *simb, *mlph;
    float *cent_a, *cent_b, *psum, *psq, *stats, *pool, *embv;
    int *rep, *nn;
    cudaGetSymbolAddress((void**)&tok_buf, g_tokens_t);
    cudaGetSymbolAddress((void**)&tok_q,  g_tokens_q);
    cudaGetSymbolAddress((void**)&skip,   g_skip);
    cudaGetSymbolAddress((void**)&tq,     g_tq);
    cudaGetSymbolAddress((void**)&tqbn,   g_tqbn);
    cudaGetSymbolAddress((void**)&Qb,     g_Qb);
    cudaGetSymbolAddress((void**)&KV,     g_KV);
    cudaGetSymbolAddress((void**)&hidb,   g_hidden);
    cudaGetSymbolAddress((void**)&simb,   g_sim);
    cudaGetSymbolAddress((void**)&mlph,   g_mlph);
    cudaGetSymbolAddress((void**)&cent_a, g_centers_a);
    cudaGetSymbolAddress((void**)&cent_b, g_centers_b);
    cudaGetSymbolAddress((void**)&psum,   g_psum);
    cudaGetSymbolAddress((void**)&psq,    g_psq);
    cudaGetSymbolAddress((void**)&stats,  g_stats);
    cudaGetSymbolAddress((void**)&pool,   g_pool);
    cudaGetSymbolAddress((void**)&embv,   g_embv);
    cudaGetSymbolAddress((void**)&rep,    g_rep);
    cudaGetSymbolAddress((void**)&nn,     g_nn);

    const int Tts[3] = {1024, 512, 256};
    const int Tqs[3] = {512, 256, 128};
    const int ks [3] = {16, 32, 64};

    const float* tok_src  = tokens;   // stage input tokens
    const float* cent_src = centers;  // stage input centers
    float* cent_dsts[3] = {cent_a, cent_b, cent_a};

    for (int i = 0; i < 3; i++) {
        int Tt = Tts[i], Tq = Tqs[i], k = ks[i];
        int Mq = BQN*Tq, Mt = BQN*Tt, Mr = Mq*k;   // Mr == 131072
        float* cent_dst = cent_dsts[i];

        fps_kernel   <<<BQN, 256>>>(cent_src, Tt, Tq, rep);
        gather_kernel<<<Mq, 256>>>(tok_src, cent_src, rep, tok_q, skip, cent_dst, Tt, Tq);
        knn_kernel   <<<Mq, 256>>>(cent_dst, cent_src, Tt, Tq, k, nn);

        const float* tok_t_cur = tok_src;
        if (i > 0) {
            bn_partial <<<64, 256>>>(tok_q, Mq, tok_src, Mt, psum, psq);
            bn_finalize<<<1, 256>>>(psum, psq, 64, Mq + Mt, stats);
            int nq = Mq*CD, nt = Mt*CD;
            bn_apply<<<(nq+255)/256, 256>>>(tok_q, tok_q, nq, stats, bn1_g + i*CD, bn1_b + i*CD);
            bn_apply<<<(nt+255)/256, 256>>>(tok_src, tok_buf, nt, stats, bn1_g + i*CD, bn1_b + i*CD);
            tok_t_cur = tok_buf;
        }

        // Q = tok_q @ wq[i]
        tf32gemm<false><<<dim3(CD/TBN, Mq/TBM), 256>>>(Mq, CD, CD, tok_q,
            nullptr, nullptr, nullptr, 0, 0, 0,
            wq + (size_t)i*CD*CD, nullptr, nullptr, Qb, 0);
        // KV = tok_t @ wkv[i]
        tf32gemm<false><<<dim3(2*CD/TBN, Mt/TBM), 256>>>(Mt, 2*CD, CD, tok_t_cur,
            nullptr, nullptr, nullptr, 0, 0, 0,
            wkv + (size_t)i*CD*2*CD, nullptr, nullptr, KV, 0);
        // hidden = relu((Q - K[nn]) @ att_w1 + b1)   [diff fused into A-load]
        tf32gemm<true><<<dim3(CD/TBN, Mr/TBM), 256>>>(Mr, CD, CD, nullptr,
            Qb, KV, nn, Tq, k, Tt,
            att_w1 + (size_t)i*CD*CD, att_b1 + i*CD, nullptr, hidb, 1);
        // sim = hidden @ att_w2 + b2
        tf32gemm<false><<<dim3(CD/TBN, Mr/TBM), 256>>>(Mr, CD, CD, hidb,
            nullptr, nullptr, nullptr, 0, 0, 0,
            att_w2 + (size_t)i*CD*CD, att_b2 + i*CD, nullptr, simb, 0);
        // softmax over neighbors + weighted V + skip
        attn_kernel<<<Mq, 256>>>(simb, KV, nn, skip, tq, Tt, Tq, k);

        // bn2 (out-of-place; tq is skip2)
        bn_partial <<<64, 256>>>(tq, Mq, nullptr, 0, psum, psq);
        bn_finalize<<<1, 256>>>(psum, psq, 64, Mq, stats);
        int n2 = Mq*CD;
        bn_apply<<<(n2+255)/256, 256>>>(tq, tqbn, n2, stats, bn2_g + i*CD, bn2_b + i*CD);

        // mlp
        tf32gemm<false><<<dim3(2*CD/TBN, Mq/TBM), 256>>>(Mq, 2*CD, CD, tqbn,
            nullptr, nullptr, nullptr, 0, 0, 0,
            mlp_w1 + (size_t)i*CD*2*CD, mlp_b1 + i*2*CD, nullptr, mlph, 1);
        tf32gemm<false><<<dim3(CD/TBN, Mq/TBM), 256>>>(Mq, CD, 2*CD, mlph,
            nullptr, nullptr, nullptr, 0, 0, 0,
            mlp_w2 + (size_t)i*2*CD*CD, mlp_b2 + i*CD, tq /*resid*/, tok_buf, 0);

        tok_src  = tok_buf;
        cent_src = cent_dst;
    }

    pool_kernel     <<<BQN, 256>>>(tok_buf, pool, 128);
    emb_kernel      <<<BQN, 512>>>(pool, emb_w, emb_b, embv);
    final_bn_kernel <<<1, 512>>>(embv, embn_g, embn_b);
    topk_norm_kernel<<<BQN, 512>>>(embv, (float*)d_out);
}

// round 4
// speedup vs baseline: 2.1833x; 1.0627x over previous
#include <cuda_runtime.h>
#include <math.h>
#include <stdint.h>

#define INF_F (__int_as_float(0x7f800000))

// ---------------- problem constants ----------------
#define BQN 16
#define T0 1024
#define CD 256
#define ED 512
#define MAXROWS 131072   // Bq*Tq*k, identical for all 3 stages

// ---------------- static device scratch ----------------
__device__ float g_tokens_t[BQN*T0*CD];
__device__ float g_tokens_q[BQN*512*CD];
__device__ float g_skip    [BQN*512*CD];
__device__ float g_tq      [BQN*512*CD];
__device__ float g_tqbn    [BQN*512*CD];
__device__ float g_Qb      [BQN*512*CD];
__device__ float g_KV      [BQN*T0*2*CD];
__device__ float g_hidden  [MAXROWS*CD];
__device__ float g_sim     [MAXROWS*CD];
__device__ float g_mlph    [BQN*512*2*CD];
__device__ float g_centers_a[BQN*T0*3];
__device__ float g_centers_b[BQN*512*3];
__device__ int   g_rep[BQN*512];
__device__ int   g_nn [MAXROWS];
__device__ float g_psum[64*CD];
__device__ float g_psq [64*CD];
__device__ float g_stats[2*CD];
__device__ float g_pool[BQN*CD];
__device__ float g_embv[BQN*ED];

// ---------------- FPS ----------------
__global__ void fps_kernel(const float* __restrict__ centers, int Tt, int Tq,
                           int* __restrict__ rep_idx) {
    int b = blockIdx.x;
    const float* P = centers + (size_t)b * Tt * 3;
    __shared__ float sx[1024], sy[1024], sz[1024];
    __shared__ float s_bv[8];
    __shared__ int   s_bi[8];
    __shared__ int   s_cur;
    int tid = threadIdx.x;
    int npt = Tt >> 8;
    float d[4];
#pragma unroll
    for (int j = 0; j < 4; j++) d[j] = INF_F;
    for (int j = tid; j < Tt; j += 256) {
        sx[j] = P[j*3+0]; sy[j] = P[j*3+1]; sz[j] = P[j*3+2];
    }
    if (tid == 0) s_cur = 0;
    __syncthreads();

    for (int step = 0; step < Tq; step++) {
        int cur = s_cur;
        if (tid == 0) rep_idx[b*Tq + step] = cur;
        float cx = sx[cur], cy = sy[cur], cz = sz[cur];
        float bv = -INF_F; int bi = 0x7fffffff;
#pragma unroll
        for (int j = 0; j < 4; j++) {
            if (j < npt) {
                int p = j*256 + tid;
                float dx = sx[p]-cx, dy = sy[p]-cy, dz = sz[p]-cz;
                float dist = dx*dx + dy*dy + dz*dz;
                float dj = fminf(d[j], dist);
                d[j] = dj;
                if (dj > bv || (dj == bv && p < bi)) { bv = dj; bi = p; }
            }
        }
#pragma unroll
        for (int off = 16; off > 0; off >>= 1) {
            float ov = __shfl_down_sync(0xffffffffu, bv, off);
            int   oi = __shfl_down_sync(0xffffffffu, bi, off);
            if (ov > bv || (ov == bv && oi < bi)) { bv = ov; bi = oi; }
        }
        if ((tid & 31) == 0) { s_bv[tid>>5] = bv; s_bi[tid>>5] = bi; }
        __syncthreads();
        if (tid == 0) {
            bv = s_bv[0]; bi = s_bi[0];
            for (int w = 1; w < 8; w++) {
                if (s_bv[w] > bv || (s_bv[w] == bv && s_bi[w] < bi)) { bv = s_bv[w]; bi = s_bi[w]; }
            }
            s_cur = bi;
        }
        __syncthreads();
    }
}

// ---------------- gather query rows ----------------
__global__ void gather_kernel(const float* __restrict__ tok_t,
                              const float* __restrict__ cent_t,
                              const int* __restrict__ rep,
                              float* __restrict__ tok_q,
                              float* __restrict__ skip,
                              float* __restrict__ cent_q,
                              int Tt, int Tq) {
    int p = blockIdx.x;
    int b = p / Tq;
    int src = rep[p];
    int c = threadIdx.x;
    float v = tok_t[(size_t)(b*Tt + src)*CD + c];
    tok_q[(size_t)p*CD + c] = v;
    skip [(size_t)p*CD + c] = v;
    if (c < 3) cent_q[p*3 + c] = cent_t[(size_t)(b*Tt + src)*3 + c];
}

// ---------------- KNN ----------------
__global__ void knn_kernel(const float* __restrict__ cent_q,
                           const float* __restrict__ cent_t,
                           int Tt, int Tq, int k, int* __restrict__ nn) {
    int p = blockIdx.x;
    int b = p / Tq;
    __shared__ float d2s[1024];
    __shared__ float s_bv[8];
    __shared__ int   s_bi[8];
    int tid = threadIdx.x;
    float qx = cent_q[p*3], qy = cent_q[p*3+1], qz = cent_q[p*3+2];
    float qq = qx*qx + qy*qy + qz*qz;
    const float* Pt = cent_t + (size_t)b*Tt*3;
    for (int t = tid; t < Tt; t += 256) {
        float tx = Pt[t*3], ty = Pt[t*3+1], tz = Pt[t*3+2];
        float tt = tx*tx + ty*ty + tz*tz;
        float dt = qx*tx + qy*ty + qz*tz;
        d2s[t] = (qq + tt) - 2.0f*dt;
    }
    __syncthreads();
    for (int sel = 0; sel < k; sel++) {
        float bv = INF_F; int bi = 0x7fffffff;
        for (int t = tid; t < Tt; t += 256) {
            float v = d2s[t];
            if (v < bv || (v == bv && t < bi)) { bv = v; bi = t; }
        }
#pragma unroll
        for (int off = 16; off > 0; off >>= 1) {
            float ov = __shfl_down_sync(0xffffffffu, bv, off);
            int   oi = __shfl_down_sync(0xffffffffu, bi, off);
            if (ov < bv || (ov == bv && oi < bi)) { bv = ov; bi = oi; }
        }
        if ((tid & 31) == 0) { s_bv[tid>>5] = bv; s_bi[tid>>5] = bi; }
        __syncthreads();
        if (tid == 0) {
            bv = s_bv[0]; bi = s_bi[0];
            for (int w = 1; w < 8; w++) {
                if (s_bv[w] < bv || (s_bv[w] == bv && s_bi[w] < bi)) { bv = s_bv[w]; bi = s_bi[w]; }
            }
            nn[p*k + sel] = bi;
            d2s[bi] = INF_F;
        }
        __syncthreads();
    }
}

// ---------------- BN stats ----------------
__global__ void bn_partial(const float* __restrict__ x1, int rows1,
                           const float* __restrict__ x2, int rows2,
                           float* __restrict__ psum, float* __restrict__ psq) {
    int c = threadIdx.x;
    int total = rows1 + rows2;
    float s = 0.f, sq = 0.f;
    for (int r = blockIdx.x; r < total; r += gridDim.x) {
        const float* row = (r < rows1) ? (x1 + (size_t)r*CD) : (x2 + (size_t)(r - rows1)*CD);
        float v = row[c];
        s += v; sq += v*v;
    }
    psum[blockIdx.x*CD + c] = s;
    psq [blockIdx.x*CD + c] = sq;
}

__global__ void bn_finalize(const float* __restrict__ psum, const float* __restrict__ psq,
                            int nb, int rows, float* __restrict__ stats) {
    int c = threadIdx.x;
    float s = 0.f, sq = 0.f;
    for (int b = 0; b < nb; b++) { s += psum[b*CD + c]; sq += psq[b*CD + c]; }
    float m = s / (float)rows;
    float v = sq / (float)rows - m*m;
    stats[c]      = m;
    stats[CD + c] = rsqrtf(v + 1e-5f);
}

__global__ void bn_apply(const float* __restrict__ in, float* __restrict__ out, int n,
                         const float* __restrict__ stats,
                         const float* __restrict__ gamma, const float* __restrict__ beta) {
    int i = blockIdx.x*blockDim.x + threadIdx.x;
    if (i >= n) return;
    int c = i & (CD-1);
    out[i] = (in[i] - stats[c]) * stats[CD + c] * gamma[c] + beta[c];
}

// ---------------- TF32 tensor-core GEMM, 2-stage cp.async pipeline ----------------
#define TBM 128
#define TBN 128
#define TBK 32
#define AS_STRIDE 36
#define BS_STRIDE 136
#define A_ELEMS (TBM*AS_STRIDE)         // 4608 floats
#define B_ELEMS (TBK*BS_STRIDE)         // 4352 floats

__device__ __forceinline__ uint32_t f2tf32(float x) {
    uint32_t r;
    asm("cvt.rna.tf32.f32 %0, %1;" : "=r"(r) : "f"(x));
    return r;
}

__device__ __forceinline__ void mma_tf32(float* c, const uint32_t* a, const uint32_t* b) {
    asm volatile(
        "mma.sync.aligned.m16n8k8.row.col.f32.tf32.tf32.f32 "
        "{%0,%1,%2,%3}, {%4,%5,%6,%7}, {%8,%9}, {%0,%1,%2,%3};\n"
        : "+f"(c[0]), "+f"(c[1]), "+f"(c[2]), "+f"(c[3])
        : "r"(a[0]), "r"(a[1]), "r"(a[2]), "r"(a[3]),
          "r"(b[0]), "r"(b[1]));
}

__device__ __forceinline__ void cp_async16(uint32_t dst, const void* src) {
    asm volatile("cp.async.cg.shared.global [%0], [%1], 16;" :: "r"(dst), "l"(src));
}
__device__ __forceinline__ void cp_commit() {
    asm volatile("cp.async.commit_group;");
}
__device__ __forceinline__ void cp_wait1() {
    asm volatile("cp.async.wait_group 1;");
}

template<bool DIFF>
__global__ __launch_bounds__(256)
void tf32gemm(int M, int N, int K,
              const float* __restrict__ A,
              const float* __restrict__ Q, const float* __restrict__ KV,
              const int* __restrict__ nn, int Tq, int knn_k, int Tt,
              const float* __restrict__ B,
              const float* __restrict__ bias, const float* __restrict__ resid,
              float* __restrict__ C, int relu) {
    extern __shared__ float smem[];
    const int STAGE = DIFF ? (2*A_ELEMS + B_ELEMS) : (A_ELEMS + B_ELEMS);

    __shared__ int sQoff[TBM];
    __shared__ int sKoff[TBM];

    int tid  = threadIdx.x;
    int lane = tid & 31;
    int warp = tid >> 5;
    int wm = warp >> 2;
    int wn = warp & 3;
    int row0 = blockIdx.y*TBM;
    int col0 = blockIdx.x*TBN;

    int ldrow = tid >> 3;        // 0..31
    int ldcol = (tid & 7) * 4;   // 0..28

    if (DIFF) {
        if (tid < TBM) {
            int r = row0 + tid;
            int p = r / knn_k;
            int b = p / Tq;
            sQoff[tid] = p * CD;
            sKoff[tid] = (b*Tt + nn[r]) * (2*CD);
        }
        __syncthreads();
    }

    // stage loader
    auto load_stage = [&](int s, int kt) {
        float* As_  = smem + s*STAGE;
        float* Akv_ = As_ + A_ELEMS;
        float* Bs_  = As_ + (DIFF ? 2*A_ELEMS : A_ELEMS);
#pragma unroll
        for (int i = 0; i < 4; i++) {
            int arow = ldrow + 32*i;
            uint32_t dA = (uint32_t)__cvta_generic_to_shared(&As_[arow*AS_STRIDE + ldcol]);
            if (DIFF) {
                cp_async16(dA, Q + sQoff[arow] + kt + ldcol);
                uint32_t dK = (uint32_t)__cvta_generic_to_shared(&Akv_[arow*AS_STRIDE + ldcol]);
                cp_async16(dK, KV + sKoff[arow] + kt + ldcol);
            } else {
                cp_async16(dA, A + (size_t)(row0 + arow)*K + kt + ldcol);
            }
        }
#pragma unroll
        for (int i = 0; i < 4; i++) {
            int bcol = ldcol + 32*i;
            uint32_t dB = (uint32_t)__cvta_generic_to_shared(&Bs_[ldrow*BS_STRIDE + bcol]);
            cp_async16(dB, B + (size_t)(kt + ldrow)*N + col0 + bcol);
        }
    };

    float acc[4][4][4];
#pragma unroll
    for (int i = 0; i < 4; i++)
#pragma unroll
        for (int j = 0; j < 4; j++)
#pragma unroll
            for (int r = 0; r < 4; r++) acc[i][j][r] = 0.f;

    const int NIT = K / TBK;
    load_stage(0, 0);
    cp_commit();

    for (int it = 0; it < NIT; it++) {
        if (it + 1 < NIT) load_stage((it+1)&1, (it+1)*TBK);
        cp_commit();
        cp_wait1();
        __syncthreads();

        int s = it & 1;
        const float* As_  = smem + s*STAGE;
        const float* Akv_ = As_ + A_ELEMS;
        const float* Bs_  = As_ + (DIFF ? 2*A_ELEMS : A_ELEMS);

#pragma unroll
        for (int kk = 0; kk < 4; kk++) {
            int kc = kk*8;
            uint32_t a[4][4];
#pragma unroll
            for (int mf = 0; mf < 4; mf++) {
                int r1 = wm*64 + mf*16 + (lane>>2);
                int i0 = r1*AS_STRIDE      + kc + (lane&3);
                int i1 = (r1+8)*AS_STRIDE  + kc + (lane&3);
                if (DIFF) {
                    a[mf][0] = f2tf32(As_[i0]     - Akv_[i0]);
                    a[mf][1] = f2tf32(As_[i1]     - Akv_[i1]);
                    a[mf][2] = f2tf32(As_[i0 + 4] - Akv_[i0 + 4]);
                    a[mf][3] = f2tf32(As_[i1 + 4] - Akv_[i1 + 4]);
                } else {
                    a[mf][0] = f2tf32(As_[i0]);
                    a[mf][1] = f2tf32(As_[i1]);
                    a[mf][2] = f2tf32(As_[i0 + 4]);
                    a[mf][3] = f2tf32(As_[i1 + 4]);
                }
            }
            uint32_t b[4][2];
#pragma unroll
            for (int nf = 0; nf < 4; nf++) {
                int ncol = wn*32 + nf*8 + (lane>>2);
                b[nf][0] = f2tf32(Bs_[(kc     + (lane&3))*BS_STRIDE + ncol]);
                b[nf][1] = f2tf32(Bs_[(kc + 4 + (lane&3))*BS_STRIDE + ncol]);
            }
#pragma unroll
            for (int mf = 0; mf < 4; mf++)
#pragma unroll
                for (int nf = 0; nf < 4; nf++)
                    mma_tf32(acc[mf][nf], a[mf], b[nf]);
        }
        __syncthreads();
    }

    // epilogue
#pragma unroll
    for (int mf = 0; mf < 4; mf++) {
#pragma unroll
        for (int nf = 0; nf < 4; nf++) {
            int r = row0 + wm*64 + mf*16 + (lane>>2);
            int c = col0 + wn*32 + nf*8 + (lane&3)*2;
#pragma unroll
            for (int half = 0; half < 2; half++) {
                int rr = r + half*8;
                float v0 = acc[mf][nf][half*2+0];
                float v1 = acc[mf][nf][half*2+1];
                if (bias)  { v0 += bias[c]; v1 += bias[c+1]; }
                if (resid) {
                    const float2 rv = *(const float2*)(resid + (size_t)rr*N + c);
                    v0 += rv.x; v1 += rv.y;
                }
                if (relu) { v0 = fmaxf(v0, 0.f); v1 = fmaxf(v1, 0.f); }
                float2 out; out.x = v0; out.y = v1;
                *(float2*)(C + (size_t)rr*N + c) = out;
            }
        }
    }
}

// ---------------- softmax over k + weighted V + skip ----------------
__global__ void attn_kernel(const float* __restrict__ sim, const float* __restrict__ KV,
                            const int* __restrict__ nn, const float* __restrict__ skip,
                            float* __restrict__ out, int Tt, int Tq, int k) {
    int p = blockIdx.x;
    int b = p / Tq;
    int c = threadIdx.x;
    __shared__ int nns[64];
    if (c < k) nns[c] = nn[p*k + c];
    __syncthreads();
    const float* S = sim + (size_t)p*k*CD;
    float m = -INF_F;
    for (int n = 0; n < k; n++) m = fmaxf(m, S[(size_t)n*CD + c]);
    float den = 0.f, acc = 0.f;
    for (int n = 0; n < k; n++) {
        float e = expf(S[(size_t)n*CD + c] - m);
        den += e;
        acc += e * KV[(size_t)(b*Tt + nns[n])*2*CD + CD + c];
    }
    out[(size_t)p*CD + c] = acc/den + skip[(size_t)p*CD + c];
}

// ---------------- final pooling / embedding ----------------
__global__ void pool_kernel(const float* __restrict__ tok, float* __restrict__ g, int Tq) {
    int b = blockIdx.x, c = threadIdx.x;
    float s = 0.f;
    for (int t = 0; t < Tq; t++) s += tok[(size_t)(b*Tq + t)*CD + c];
    g[b*CD + c] = s / (float)Tq;
}

__global__ void emb_kernel(const float* __restrict__ g, const float* __restrict__ W,
                           const float* __restrict__ bias, float* __restrict__ out) {
    int b = blockIdx.x, e = threadIdx.x;
    __shared__ float gs[CD];
    if (e < CD) gs[e] = g[b*CD + e];
    __syncthreads();
    float s = 0.f;
    for (int c = 0; c < CD; c++) s += gs[c] * W[(size_t)c*ED + e];
    out[b*ED + e] = s + bias[e];
}

__global__ void final_bn_kernel(float* __restrict__ x, const float* __restrict__ gamma,
                                const float* __restrict__ beta) {
    int e = threadIdx.x;
    float s = 0.f;
    for (int b = 0; b < BQN; b++) s += x[b*ED + e];
    float m = s / (float)BQN;
    float v = 0.f;
    for (int b = 0; b < BQN; b++) { float d = x[b*ED + e] - m; v += d*d; }
    v /= (float)BQN;
    float rs = rsqrtf(v + 1e-5f);
    for (int b = 0; b < BQN; b++) {
        float val = (x[b*ED + e] - m) * rs * gamma[e] + beta[e];
        x[b*ED + e] = fmaxf(val, 0.f);
    }
}

__global__ void topk_norm_kernel(const float* __restrict__ x, float* __restrict__ out) {
    int b = blockIdx.x, t = threadIdx.x;
    __shared__ float vals[ED], work[ED];
    __shared__ float red[16];
    __shared__ int   redi[16];
    __shared__ float s_thr, s_norm;
    float v = x[b*ED + t];
    vals[t] = v; work[t] = v;
    __syncthreads();
    for (int it = 0; it < 64; it++) {
        float bv = work[t]; int bi = t;
#pragma unroll
        for (int off = 16; off > 0; off >>= 1) {
            float ov = __shfl_down_sync(0xffffffffu, bv, off);
            int   oi = __shfl_down_sync(0xffffffffu, bi, off);
            if (ov > bv) { bv = ov; bi = oi; }
        }
        if ((t & 31) == 0) { red[t>>5] = bv; redi[t>>5] = bi; }
        __syncthreads();
        if (t == 0) {
            bv = red[0]; bi = redi[0];
            for (int w = 1; w < 16; w++) if (red[w] > bv) { bv = red[w]; bi = redi[w]; }
            work[bi] = -INF_F;
            if (it == 63) s_thr = bv;
        }
        __syncthreads();
    }
    float thr = s_thr;
    float kept = (vals[t] >= thr) ? vals[t] : 0.f;
    float sq = kept*kept;
#pragma unroll
    for (int off = 16; off > 0; off >>= 1) sq += __shfl_down_sync(0xffffffffu, sq, off);
    if ((t & 31) == 0) red[t>>5] = sq;
    __syncthreads();
    if (t == 0) {
        float s = 0.f;
        for (int w = 0; w < 16; w++) s += red[w];
        s_norm = fmaxf(sqrtf(s), 1e-12f);
    }
    __syncthreads();
    out[b*ED + t] = kept / s_norm;
}

// ---------------- host orchestration ----------------
extern "C" void kernel_launch(void* const* d_in, const int* in_sizes, int n_in,
                              void* d_out, int out_size) {
    const float* tokens = (const float*)d_in[0];
    const float* centers = (const float*)d_in[1];
    const float* wq     = (const float*)d_in[3];
    const float* wkv    = (const float*)d_in[4];
    const float* mlp_w1 = (const float*)d_in[5];
    const float* mlp_b1 = (const float*)d_in[6];
    const float* mlp_w2 = (const float*)d_in[7];
    const float* mlp_b2 = (const float*)d_in[8];
    const float* bn1_g  = (const float*)d_in[9];
    const float* bn1_b  = (const float*)d_in[10];
    const float* bn2_g  = (const float*)d_in[11];
    const float* bn2_b  = (const float*)d_in[12];
    const float* att_w1 = (const float*)d_in[13];
    const float* att_b1 = (const float*)d_in[14];
    const float* att_w2 = (const float*)d_in[15];
    const float* att_b2 = (const float*)d_in[16];
    const float* emb_w  = (const float*)d_in[17];
    const float* emb_b  = (const float*)d_in[18];
    const float* embn_g = (const float*)d_in[19];
    const float* embn_b = (const float*)d_in[20];

    float *tok_buf, *tok_q, *skip, *tq, *tqbn, *Qb, *KV, *hidb, *simb, *mlph;
    float *cent_a, *cent_b, *psum, *psq, *stats, *pool, *embv;
    int *rep, *nn;
    cudaGetSymbolAddress((void**)&tok_buf, g_tokens_t);
    cudaGetSymbolAddress((void**)&tok_q,  g_tokens_q);
    cudaGetSymbolAddress((void**)&skip,   g_skip);
    cudaGetSymbolAddress((void**)&tq,     g_tq);
    cudaGetSymbolAddress((void**)&tqbn,   g_tqbn);
    cudaGetSymbolAddress((void**)&Qb,     g_Qb);
    cudaGetSymbolAddress((void**)&KV,     g_KV);
    cudaGetSymbolAddress((void**)&hidb,   g_hidden);
    cudaGetSymbolAddress((void**)&simb,   g_sim);
    cudaGetSymbolAddress((void**)&mlph,   g_mlph);
    cudaGetSymbolAddress((void**)&cent_a, g_centers_a);
    cudaGetSymbolAddress((void**)&cent_b, g_centers_b);
    cudaGetSymbolAddress((void**)&psum,   g_psum);
    cudaGetSymbolAddress((void**)&psq,    g_psq);
    cudaGetSymbolAddress((void**)&stats,  g_stats);
    cudaGetSymbolAddress((void**)&pool,   g_pool);
    cudaGetSymbolAddress((void**)&embv,   g_embv);
    cudaGetSymbolAddress((void**)&rep,    g_rep);
    cudaGetSymbolAddress((void**)&nn,     g_nn);

    const int SMEM_PLAIN = 2*(A_ELEMS + B_ELEMS)*sizeof(float);     // ~71.7KB
    const int SMEM_DIFF  = 2*(2*A_ELEMS + B_ELEMS)*sizeof(float);   // ~108.5KB
    static bool attr_set = false;
    if (!attr_set) {
        cudaFuncSetAttribute(tf32gemm<false>, cudaFuncAttributeMaxDynamicSharedMemorySize, SMEM_PLAIN);
        cudaFuncSetAttribute(tf32gemm<true>,  cudaFuncAttributeMaxDynamicSharedMemorySize, SMEM_DIFF);
        attr_set = true;
    }

    const int Tts[3] = {1024, 512, 256};
    const int Tqs[3] = {512, 256, 128};
    const int ks [3] = {16, 32, 64};

    const float* tok_src  = tokens;
    const float* cent_src = centers;
    float* cent_dsts[3] = {cent_a, cent_b, cent_a};

    for (int i = 0; i < 3; i++) {
        int Tt = Tts[i], Tq = Tqs[i], k = ks[i];
        int Mq = BQN*Tq, Mt = BQN*Tt, Mr = Mq*k;
        float* cent_dst = cent_dsts[i];

        fps_kernel   <<<BQN, 256>>>(cent_src, Tt, Tq, rep);
        gather_kernel<<<Mq, 256>>>(tok_src, cent_src, rep, tok_q, skip, cent_dst, Tt, Tq);
        knn_kernel   <<<Mq, 256>>>(cent_dst, cent_src, Tt, Tq, k, nn);

        const float* tok_t_cur = tok_src;
        if (i > 0) {
            bn_partial <<<64, 256>>>(tok_q, Mq, tok_src, Mt, psum, psq);
            bn_finalize<<<1, 256>>>(psum, psq, 64, Mq + Mt, stats);
            int nq = Mq*CD, nt = Mt*CD;
            bn_apply<<<(nq+255)/256, 256>>>(tok_q, tok_q, nq, stats, bn1_g + i*CD, bn1_b + i*CD);
            bn_apply<<<(nt+255)/256, 256>>>(tok_src, tok_buf, nt, stats, bn1_g + i*CD, bn1_b + i*CD);
            tok_t_cur = tok_buf;
        }

        tf32gemm<false><<<dim3(CD/TBN, Mq/TBM), 256, SMEM_PLAIN>>>(Mq, CD, CD, tok_q,
            nullptr, nullptr, nullptr, 0, 0, 0,
            wq + (size_t)i*CD*CD, nullptr, nullptr, Qb, 0);
        tf32gemm<false><<<dim3(2*CD/TBN, Mt/TBM), 256, SMEM_PLAIN>>>(Mt, 2*CD, CD, tok_t_cur,
            nullptr, nullptr, nullptr, 0, 0, 0,
            wkv + (size_t)i*CD*2*CD, nullptr, nullptr, KV, 0);
        tf32gemm<true><<<dim3(CD/TBN, Mr/TBM), 256, SMEM_DIFF>>>(Mr, CD, CD, nullptr,
            Qb, KV, nn, Tq, k, Tt,
            att_w1 + (size_t)i*CD*CD, att_b1 + i*CD, nullptr, hidb, 1);
        tf32gemm<false><<<dim3(CD/TBN, Mr/TBM), 256, SMEM_PLAIN>>>(Mr, CD, CD, hidb,
            nullptr, nullptr, nullptr, 0, 0, 0,
            att_w2 + (size_t)i*CD*CD, att_b2 + i*CD, nullptr, simb, 0);
        attn_kernel<<<Mq, 256>>>(simb, KV, nn, skip, tq, Tt, Tq, k);

        bn_partial <<<64, 256>>>(tq, Mq, nullptr, 0, psum, psq);
        bn_finalize<<<1, 256>>>(psum, psq, 64, Mq, stats);
        int n2 = Mq*CD;
        bn_apply<<<(n2+255)/256, 256>>>(tq, tqbn, n2, stats, bn2_g + i*CD, bn2_b + i*CD);

        tf32gemm<false><<<dim3(2*CD/TBN, Mq/TBM), 256, SMEM_PLAIN>>>(Mq, 2*CD, CD, tqbn,
            nullptr, nullptr, nullptr, 0, 0, 0,
            mlp_w1 + (size_t)i*CD*2*CD, mlp_b1 + i*2*CD, nullptr, mlph, 1);
        tf32gemm<false><<<dim3(CD/TBN, Mq/TBM), 256, SMEM_PLAIN>>>(Mq, CD, 2*CD, mlph,
            nullptr, nullptr, nullptr, 0, 0, 0,
            mlp_w2 + (size_t)i*2*CD*CD, mlp_b2 + i*CD, tq, tok_buf, 0);

        tok_src  = tok_buf;
        cent_src = cent_dst;
    }

    pool_kernel     <<<BQN, 256>>>(tok_buf, pool, 128);
    emb_kernel      <<<BQN, 512>>>(pool, emb_w, emb_b, embv);
    final_bn_kernel <<<1, 512>>>(embv, embn_g, embn_b);
    topk_norm_kernel<<<BQN, 512>>>(embv, (float*)d_out);
}

// round 5
// speedup vs baseline: 2.2679x; 1.0388x over previous
#include <cuda_runtime.h>
#include <math.h>
#include <stdint.h>

#define INF_F (__int_as_float(0x7f800000))

// ---------------- problem constants ----------------
#define BQN 16
#define T0 1024
#define CD 256
#define ED 512
#define MAXROWS 131072

// ---------------- static device scratch ----------------
__device__ float g_tokens_t[BQN*T0*CD];
__device__ float g_tokens_q[BQN*512*CD];
__device__ float g_skip    [BQN*512*CD];
__device__ float g_tq      [BQN*512*CD];
__device__ float g_tqbn    [BQN*512*CD];
__device__ float g_Qb      [BQN*512*CD];
__device__ float g_KV      [BQN*T0*2*CD];
__device__ float g_hidden  [MAXROWS*CD];
__device__ float g_mlph    [BQN*512*2*CD];
__device__ float g_centers_a[BQN*T0*3];
__device__ float g_centers_b[BQN*512*3];
__device__ int   g_rep[BQN*512];
__device__ int   g_nn [MAXROWS];
__device__ float g_psum[64*CD];
__device__ float g_psq [64*CD];
__device__ float g_stats[2*CD];
__device__ float g_pool[BQN*CD];
__device__ float g_embv[BQN*ED];

// ---------------- FPS ----------------
__global__ void fps_kernel(const float* __restrict__ centers, int Tt, int Tq,
                           int* __restrict__ rep_idx) {
    int b = blockIdx.x;
    const float* P = centers + (size_t)b * Tt * 3;
    __shared__ float sx[1024], sy[1024], sz[1024];
    __shared__ float s_bv[8];
    __shared__ int   s_bi[8];
    __shared__ int   s_cur;
    int tid = threadIdx.x;
    int npt = Tt >> 8;
    float d[4];
#pragma unroll
    for (int j = 0; j < 4; j++) d[j] = INF_F;
    for (int j = tid; j < Tt; j += 256) {
        sx[j] = P[j*3+0]; sy[j] = P[j*3+1]; sz[j] = P[j*3+2];
    }
    if (tid == 0) s_cur = 0;
    __syncthreads();

    for (int step = 0; step < Tq; step++) {
        int cur = s_cur;
        if (tid == 0) rep_idx[b*Tq + step] = cur;
        float cx = sx[cur], cy = sy[cur], cz = sz[cur];
        float bv = -INF_F; int bi = 0x7fffffff;
#pragma unroll
        for (int j = 0; j < 4; j++) {
            if (j < npt) {
                int p = j*256 + tid;
                float dx = sx[p]-cx, dy = sy[p]-cy, dz = sz[p]-cz;
                float dist = dx*dx + dy*dy + dz*dz;
                float dj = fminf(d[j], dist);
                d[j] = dj;
                if (dj > bv || (dj == bv && p < bi)) { bv = dj; bi = p; }
            }
        }
#pragma unroll
        for (int off = 16; off > 0; off >>= 1) {
            float ov = __shfl_down_sync(0xffffffffu, bv, off);
            int   oi = __shfl_down_sync(0xffffffffu, bi, off);
            if (ov > bv || (ov == bv && oi < bi)) { bv = ov; bi = oi; }
        }
        if ((tid & 31) == 0) { s_bv[tid>>5] = bv; s_bi[tid>>5] = bi; }
        __syncthreads();
        if (tid == 0) {
            bv = s_bv[0]; bi = s_bi[0];
            for (int w = 1; w < 8; w++) {
                if (s_bv[w] > bv || (s_bv[w] == bv && s_bi[w] < bi)) { bv = s_bv[w]; bi = s_bi[w]; }
            }
            s_cur = bi;
        }
        __syncthreads();
    }
}

// ---------------- gather query rows ----------------
__global__ void gather_kernel(const float* __restrict__ tok_t,
                              const float* __restrict__ cent_t,
                              const int* __restrict__ rep,
                              float* __restrict__ tok_q,
                              float* __restrict__ skip,
                              float* __restrict__ cent_q,
                              int Tt, int Tq) {
    int p = blockIdx.x;
    int b = p / Tq;
    int src = rep[p];
    int c = threadIdx.x;
    float v = tok_t[(size_t)(b*Tt + src)*CD + c];
    tok_q[(size_t)p*CD + c] = v;
    skip [(size_t)p*CD + c] = v;
    if (c < 3) cent_q[p*3 + c] = cent_t[(size_t)(b*Tt + src)*3 + c];
}

// ---------------- KNN ----------------
__global__ void knn_kernel(const float* __restrict__ cent_q,
                           const float* __restrict__ cent_t,
                           int Tt, int Tq, int k, int* __restrict__ nn) {
    int p = blockIdx.x;
    int b = p / Tq;
    __shared__ float d2s[1024];
    __shared__ float s_bv[8];
    __shared__ int   s_bi[8];
    int tid = threadIdx.x;
    float qx = cent_q[p*3], qy = cent_q[p*3+1], qz = cent_q[p*3+2];
    float qq = qx*qx + qy*qy + qz*qz;
    const float* Pt = cent_t + (size_t)b*Tt*3;
    for (int t = tid; t < Tt; t += 256) {
        float tx = Pt[t*3], ty = Pt[t*3+1], tz = Pt[t*3+2];
        float tt = tx*tx + ty*ty + tz*tz;
        float dt = qx*tx + qy*ty + qz*tz;
        d2s[t] = (qq + tt) - 2.0f*dt;
    }
    __syncthreads();
    for (int sel = 0; sel < k; sel++) {
        float bv = INF_F; int bi = 0x7fffffff;
        for (int t = tid; t < Tt; t += 256) {
            float v = d2s[t];
            if (v < bv || (v == bv && t < bi)) { bv = v; bi = t; }
        }
#pragma unroll
        for (int off = 16; off > 0; off >>= 1) {
            float ov = __shfl_down_sync(0xffffffffu, bv, off);
            int   oi = __shfl_down_sync(0xffffffffu, bi, off);
            if (ov < bv || (ov == bv && oi < bi)) { bv = ov; bi = oi; }
        }
        if ((tid & 31) == 0) { s_bv[tid>>5] = bv; s_bi[tid>>5] = bi; }
        __syncthreads();
        if (tid == 0) {
            bv = s_bv[0]; bi = s_bi[0];
            for (int w = 1; w < 8; w++) {
                if (s_bv[w] < bv || (s_bv[w] == bv && s_bi[w] < bi)) { bv = s_bv[w]; bi = s_bi[w]; }
            }
            nn[p*k + sel] = bi;
            d2s[bi] = INF_F;
        }
        __syncthreads();
    }
}

// ---------------- BN stats ----------------
__global__ void bn_partial(const float* __restrict__ x1, int rows1,
                           const float* __restrict__ x2, int rows2,
                           float* __restrict__ psum, float* __restrict__ psq) {
    int c = threadIdx.x;
    int total = rows1 + rows2;
    float s = 0.f, sq = 0.f;
    for (int r = blockIdx.x; r < total; r += gridDim.x) {
        const float* row = (r < rows1) ? (x1 + (size_t)r*CD) : (x2 + (size_t)(r - rows1)*CD);
        float v = row[c];
        s += v; sq += v*v;
    }
    psum[blockIdx.x*CD + c] = s;
    psq [blockIdx.x*CD + c] = sq;
}

__global__ void bn_finalize(const float* __restrict__ psum, const float* __restrict__ psq,
                            int nb, int rows, float* __restrict__ stats) {
    int c = threadIdx.x;
    float s = 0.f, sq = 0.f;
    for (int b = 0; b < nb; b++) { s += psum[b*CD + c]; sq += psq[b*CD + c]; }
    float m = s / (float)rows;
    float v = sq / (float)rows - m*m;
    stats[c]      = m;
    stats[CD + c] = rsqrtf(v + 1e-5f);
}

__global__ void bn_apply(const float* __restrict__ in, float* __restrict__ out, int n,
                         const float* __restrict__ stats,
                         const float* __restrict__ gamma, const float* __restrict__ beta) {
    int i = blockIdx.x*blockDim.x + threadIdx.x;
    if (i >= n) return;
    int c = i & (CD-1);
    out[i] = (in[i] - stats[c]) * stats[CD + c] * gamma[c] + beta[c];
}

// ---------------- TF32 tensor-core GEMM, 2-stage cp.async pipeline ----------------
// Raw fp32 bits are fed to mma.tf32 (HW uses the tf32 subset of the bits).
#define TBM 128
#define TBN 128
#define TBK 32
#define AS_STRIDE 36
#define BS_STRIDE 136
#define A_ELEMS (TBM*AS_STRIDE)
#define B_ELEMS (TBK*BS_STRIDE)

__device__ __forceinline__ void mma_tf32(float* c, const uint32_t* a, const uint32_t* b) {
    asm volatile(
        "mma.sync.aligned.m16n8k8.row.col.f32.tf32.tf32.f32 "
        "{%0,%1,%2,%3}, {%4,%5,%6,%7}, {%8,%9}, {%0,%1,%2,%3};\n"
        : "+f"(c[0]), "+f"(c[1]), "+f"(c[2]), "+f"(c[3])
        : "r"(a[0]), "r"(a[1]), "r"(a[2]), "r"(a[3]),
          "r"(b[0]), "r"(b[1]));
}

__device__ __forceinline__ void cp_async16(uint32_t dst, const void* src) {
    asm volatile("cp.async.cg.shared.global [%0], [%1], 16;" :: "r"(dst), "l"(src));
}
__device__ __forceinline__ void cp_commit() {
    asm volatile("cp.async.commit_group;");
}
__device__ __forceinline__ void cp_wait1() {
    asm volatile("cp.async.wait_group 1;");
}

// ---- mainloop body shared by the GEMM kernels (macro-free via template) ----
template<bool DIFF>
__device__ __forceinline__ void gemm_mainloop(
    float acc[4][4][4],
    const float* __restrict__ A, const float* __restrict__ Q, const float* __restrict__ KV,
    const int* sQoff, const int* sKoff,
    const float* __restrict__ B,
    int K, int N, int row0, int col0,
    float* smem, int STAGE,
    int tid, int lane, int wm, int wn)
{
    int ldrow = tid >> 3;
    int ldcol = (tid & 7) * 4;

    auto load_stage = [&](int s, int kt) {
        float* As_  = smem + s*STAGE;
        float* Akv_ = As_ + A_ELEMS;
        float* Bs_  = As_ + (DIFF ? 2*A_ELEMS : A_ELEMS);
#pragma unroll
        for (int i = 0; i < 4; i++) {
            int arow = ldrow + 32*i;
            uint32_t dA = (uint32_t)__cvta_generic_to_shared(&As_[arow*AS_STRIDE + ldcol]);
            if (DIFF) {
                cp_async16(dA, Q + sQoff[arow] + kt + ldcol);
                uint32_t dK = (uint32_t)__cvta_generic_to_shared(&Akv_[arow*AS_STRIDE + ldcol]);
                cp_async16(dK, KV + sKoff[arow] + kt + ldcol);
            } else {
                cp_async16(dA, A + (size_t)(row0 + arow)*K + kt + ldcol);
            }
        }
#pragma unroll
        for (int i = 0; i < 4; i++) {
            int bcol = ldcol + 32*i;
            uint32_t dB = (uint32_t)__cvta_generic_to_shared(&Bs_[ldrow*BS_STRIDE + bcol]);
            cp_async16(dB, B + (size_t)(kt + ldrow)*N + col0 + bcol);
        }
    };

    const int NIT = K / TBK;
    load_stage(0, 0);
    cp_commit();

    for (int it = 0; it < NIT; it++) {
        if (it + 1 < NIT) load_stage((it+1)&1, (it+1)*TBK);
        cp_commit();
        cp_wait1();
        __syncthreads();

        int s = it & 1;
        const float* As_  = smem + s*STAGE;
        const float* Akv_ = As_ + A_ELEMS;
        const float* Bs_  = As_ + (DIFF ? 2*A_ELEMS : A_ELEMS);

#pragma unroll
        for (int kk = 0; kk < 4; kk++) {
            int kc = kk*8;
            uint32_t a[4][4];
#pragma unroll
            for (int mf = 0; mf < 4; mf++) {
                int r1 = wm*64 + mf*16 + (lane>>2);
                int i0 = r1*AS_STRIDE      + kc + (lane&3);
                int i1 = (r1+8)*AS_STRIDE  + kc + (lane&3);
                if (DIFF) {
                    a[mf][0] = __float_as_uint(As_[i0]     - Akv_[i0]);
                    a[mf][1] = __float_as_uint(As_[i1]     - Akv_[i1]);
                    a[mf][2] = __float_as_uint(As_[i0 + 4] - Akv_[i0 + 4]);
                    a[mf][3] = __float_as_uint(As_[i1 + 4] - Akv_[i1 + 4]);
                } else {
                    a[mf][0] = __float_as_uint(As_[i0]);
                    a[mf][1] = __float_as_uint(As_[i1]);
                    a[mf][2] = __float_as_uint(As_[i0 + 4]);
                    a[mf][3] = __float_as_uint(As_[i1 + 4]);
                }
            }
            uint32_t b[4][2];
#pragma unroll
            for (int nf = 0; nf < 4; nf++) {
                int ncol = wn*32 + nf*8 + (lane>>2);
                b[nf][0] = __float_as_uint(Bs_[(kc     + (lane&3))*BS_STRIDE + ncol]);
                b[nf][1] = __float_as_uint(Bs_[(kc + 4 + (lane&3))*BS_STRIDE + ncol]);
            }
#pragma unroll
            for (int mf = 0; mf < 4; mf++)
#pragma unroll
                for (int nf = 0; nf < 4; nf++)
                    mma_tf32(acc[mf][nf], a[mf], b[nf]);
        }
        __syncthreads();
    }
}

template<bool DIFF>
__global__ __launch_bounds__(256)
void tf32gemm(int M, int N, int K,
              const float* __restrict__ A,
              const float* __restrict__ Q, const float* __restrict__ KV,
              const int* __restrict__ nn, int Tq, int knn_k, int Tt,
              const float* __restrict__ B,
              const float* __restrict__ bias, const float* __restrict__ resid,
              float* __restrict__ C, int relu) {
    extern __shared__ float smem[];
    const int STAGE = DIFF ? (2*A_ELEMS + B_ELEMS) : (A_ELEMS + B_ELEMS);
    __shared__ int sQoff[TBM];
    __shared__ int sKoff[TBM];

    int tid  = threadIdx.x;
    int lane = tid & 31;
    int warp = tid >> 5;
    int wm = warp >> 2;
    int wn = warp & 3;
    int row0 = blockIdx.y*TBM;
    int col0 = blockIdx.x*TBN;

    if (DIFF) {
        if (tid < TBM) {
            int r = row0 + tid;
            int p = r / knn_k;
            int b = p / Tq;
            sQoff[tid] = p * CD;
            sKoff[tid] = (b*Tt + nn[r]) * (2*CD);
        }
        __syncthreads();
    }

    float acc[4][4][4];
#pragma unroll
    for (int i = 0; i < 4; i++)
#pragma unroll
        for (int j = 0; j < 4; j++)
#pragma unroll
            for (int r = 0; r < 4; r++) acc[i][j][r] = 0.f;

    gemm_mainloop<DIFF>(acc, A, Q, KV, sQoff, sKoff, B, K, N, row0, col0,
                        smem, STAGE, tid, lane, wm, wn);

#pragma unroll
    for (int mf = 0; mf < 4; mf++) {
#pragma unroll
        for (int nf = 0; nf < 4; nf++) {
            int r = row0 + wm*64 + mf*16 + (lane>>2);
            int c = col0 + wn*32 + nf*8 + (lane&3)*2;
#pragma unroll
            for (int half = 0; half < 2; half++) {
                int rr = r + half*8;
                float v0 = acc[mf][nf][half*2+0];
                float v1 = acc[mf][nf][half*2+1];
                if (bias)  { v0 += bias[c]; v1 += bias[c+1]; }
                if (resid) {
                    const float2 rv = *(const float2*)(resid + (size_t)rr*N + c);
                    v0 += rv.x; v1 += rv.y;
                }
                if (relu) { v0 = fmaxf(v0, 0.f); v1 = fmaxf(v1, 0.f); }
                float2 out; out.x = v0; out.y = v1;
                *(float2*)(C + (size_t)rr*N + c) = out;
            }
        }
    }
}

// ---- GEMM2 fused with per-column softmax over k, V-gather, skip add ----
// sim tile (128 x 128) -> smem -> softmax over the k rows of each point ->
// out[p, col] = sum_n softmax(sim)[n] * V[nn[p,n], col] + skip[p, col]
#define SIM_STRIDE 132
__global__ __launch_bounds__(256)
void tf32gemm_attn(int M, int N, int K,
                   const float* __restrict__ A,        // hidden
                   const float* __restrict__ B,        // att_w2
                   const float* __restrict__ bias,     // att_b2
                   const float* __restrict__ KV,
                   const int* __restrict__ nn, int Tq, int knn_k, int Tt,
                   const float* __restrict__ skipb,
                   float* __restrict__ out) {
    extern __shared__ float smem[];
    const int STAGE = A_ELEMS + B_ELEMS;
    __shared__ int sVoff[TBM];

    int tid  = threadIdx.x;
    int lane = tid & 31;
    int warp = tid >> 5;
    int wm = warp >> 2;
    int wn = warp & 3;
    int row0 = blockIdx.y*TBM;
    int col0 = blockIdx.x*TBN;

    if (tid < TBM) {
        int r = row0 + tid;
        int p = r / knn_k;
        int b = p / Tq;
        sVoff[tid] = (b*Tt + nn[r]) * (2*CD) + CD;
    }

    float acc[4][4][4];
#pragma unroll
    for (int i = 0; i < 4; i++)
#pragma unroll
        for (int j = 0; j < 4; j++)
#pragma unroll
            for (int r = 0; r < 4; r++) acc[i][j][r] = 0.f;

    gemm_mainloop<false>(acc, A, nullptr, nullptr, nullptr, nullptr, B, K, N, row0, col0,
                         smem, STAGE, tid, lane, wm, wn);

    // write sim tile (+bias) to smem
    float* sim_s = smem;   // 128 x SIM_STRIDE, fits in stage buffers
#pragma unroll
    for (int mf = 0; mf < 4; mf++) {
#pragma unroll
        for (int nf = 0; nf < 4; nf++) {
            int r = wm*64 + mf*16 + (lane>>2);
            int c = wn*32 + nf*8 + (lane&3)*2;
#pragma unroll
            for (int half = 0; half < 2; half++) {
                int rr = r + half*8;
                float v0 = acc[mf][nf][half*2+0] + bias[col0 + c];
                float v1 = acc[mf][nf][half*2+1] + bias[col0 + c + 1];
                sim_s[rr*SIM_STRIDE + c]     = v0;
                sim_s[rr*SIM_STRIDE + c + 1] = v1;
            }
        }
    }
    __syncthreads();

    // softmax over k rows per (point, col), V gather, skip add
    int ppb = TBM / knn_k;          // points per block: 8 / 4 / 2
    int col = tid & 127;
    int cg  = col0 + col;
    for (int pp = tid >> 7; pp < ppb; pp += 2) {
        const float* Sp = sim_s + (pp*knn_k)*SIM_STRIDE + col;
        float m = -INF_F;
        for (int n = 0; n < knn_k; n++) m = fmaxf(m, Sp[n*SIM_STRIDE]);
        float den = 0.f, accv = 0.f;
        for (int n = 0; n < knn_k; n++) {
            float e = expf(Sp[n*SIM_STRIDE] - m);
            den += e;
            accv += e * KV[(size_t)sVoff[pp*knn_k + n] + cg];
        }
        int pg = row0/knn_k + pp;
        out[(size_t)pg*CD + cg] = accv/den + skipb[(size_t)pg*CD + cg];
    }
}

// ---------------- final pooling / embedding ----------------
__global__ void pool_kernel(const float* __restrict__ tok, float* __restrict__ g, int Tq) {
    int b = blockIdx.x, c = threadIdx.x;
    float s = 0.f;
    for (int t = 0; t < Tq; t++) s += tok[(size_t)(b*Tq + t)*CD + c];
    g[b*CD + c] = s / (float)Tq;
}

__global__ void emb_kernel(const float* __restrict__ g, const float* __restrict__ W,
                           const float* __restrict__ bias, float* __restrict__ out) {
    int b = blockIdx.x, e = threadIdx.x;
    __shared__ float gs[CD];
    if (e < CD) gs[e] = g[b*CD + e];
    __syncthreads();
    float s = 0.f;
    for (int c = 0; c < CD; c++) s += gs[c] * W[(size_t)c*ED + e];
    out[b*ED + e] = s + bias[e];
}

__global__ void final_bn_kernel(float* __restrict__ x, const float* __restrict__ gamma,
                                const float* __restrict__ beta) {
    int e = threadIdx.x;
    float s = 0.f;
    for (int b = 0; b < BQN; b++) s += x[b*ED + e];
    float m = s / (float)BQN;
    float v = 0.f;
    for (int b = 0; b < BQN; b++) { float d = x[b*ED + e] - m; v += d*d; }
    v /= (float)BQN;
    float rs = rsqrtf(v + 1e-5f);
    for (int b = 0; b < BQN; b++) {
        float val = (x[b*ED + e] - m) * rs * gamma[e] + beta[e];
        x[b*ED + e] = fmaxf(val, 0.f);
    }
}

__global__ void topk_norm_kernel(const float* __restrict__ x, float* __restrict__ out) {
    int b = blockIdx.x, t = threadIdx.x;
    __shared__ float vals[ED], work[ED];
    __shared__ float red[16];
    __shared__ int   redi[16];
    __shared__ float s_thr, s_norm;
    float v = x[b*ED + t];
    vals[t] = v; work[t] = v;
    __syncthreads();
    for (int it = 0; it < 64; it++) {
        float bv = work[t]; int bi = t;
#pragma unroll
        for (int off = 16; off > 0; off >>= 1) {
            float ov = __shfl_down_sync(0xffffffffu, bv, off);
            int   oi = __shfl_down_sync(0xffffffffu, bi, off);
            if (ov > bv) { bv = ov; bi = oi; }
        }
        if ((t & 31) == 0) { red[t>>5] = bv; redi[t>>5] = bi; }
        __syncthreads();
        if (t == 0) {
            bv = red[0]; bi = redi[0];
            for (int w = 1; w < 16; w++) if (red[w] > bv) { bv = red[w]; bi = redi[w]; }
            work[bi] = -INF_F;
            if (it == 63) s_thr = bv;
        }
        __syncthreads();
    }
    float thr = s_thr;
    float kept = (vals[t] >= thr) ? vals[t] : 0.f;
    float sq = kept*kept;
#pragma unroll
    for (int off = 16; off > 0; off >>= 1) sq += __shfl_down_sync(0xffffffffu, sq, off);
    if ((t & 31) == 0) red[t>>5] = sq;
    __syncthreads();
    if (t == 0) {
        float s = 0.f;
        for (int w = 0; w < 16; w++) s += red[w];
        s_norm = fmaxf(sqrtf(s), 1e-12f);
    }
    __syncthreads();
    out[b*ED + t] = kept / s_norm;
}

// ---------------- host orchestration ----------------
extern "C" void kernel_launch(void* const* d_in, const int* in_sizes, int n_in,
                              void* d_out, int out_size) {
    const float* tokens = (const float*)d_in[0];
    const float* centers = (const float*)d_in[1];
    const float* wq     = (const float*)d_in[3];
    const float* wkv    = (const float*)d_in[4];
    const float* mlp_w1 = (const float*)d_in[5];
    const float* mlp_b1 = (const float*)d_in[6];
    const float* mlp_w2 = (const float*)d_in[7];
    const float* mlp_b2 = (const float*)d_in[8];
    const float* bn1_g  = (const float*)d_in[9];
    const float* bn1_b  = (const float*)d_in[10];
    const float* bn2_g  = (const float*)d_in[11];
    const float* bn2_b  = (const float*)d_in[12];
    const float* att_w1 = (const float*)d_in[13];
    const float* att_b1 = (const float*)d_in[14];
    const float* att_w2 = (const float*)d_in[15];
    const float* att_b2 = (const float*)d_in[16];
    const float* emb_w  = (const float*)d_in[17];
    const float* emb_b  = (const float*)d_in[18];
    const float* embn_g = (const float*)d_in[19];
    const float* embn_b = (const float*)d_in[20];

    float *tok_buf, *tok_q, *skip, *tq, *tqbn, *Qb, *KV, *hidb, *mlph;
    float *cent_a, *cent_b, *psum, *psq, *stats, *pool, *embv;
    int *rep, *nn;
    cudaGetSymbolAddress((void**)&tok_buf, g_tokens_t);
    cudaGetSymbolAddress((void**)&tok_q,  g_tokens_q);
    cudaGetSymbolAddress((void**)&skip,   g_skip);
    cudaGetSymbolAddress((void**)&tq,     g_tq);
    cudaGetSymbolAddress((void**)&tqbn,   g_tqbn);
    cudaGetSymbolAddress((void**)&Qb,     g_Qb);
    cudaGetSymbolAddress((void**)&KV,     g_KV);
    cudaGetSymbolAddress((void**)&hidb,   g_hidden);
    cudaGetSymbolAddress((void**)&mlph,   g_mlph);
    cudaGetSymbolAddress((void**)&cent_a, g_centers_a);
    cudaGetSymbolAddress((void**)&cent_b, g_centers_b);
    cudaGetSymbolAddress((void**)&psum,   g_psum);
    cudaGetSymbolAddress((void**)&psq,    g_psq);
    cudaGetSymbolAddress((void**)&stats,  g_stats);
    cudaGetSymbolAddress((void**)&pool,   g_pool);
    cudaGetSymbolAddress((void**)&embv,   g_embv);
    cudaGetSymbolAddress((void**)&rep,    g_rep);
    cudaGetSymbolAddress((void**)&nn,     g_nn);

    const int SMEM_PLAIN = 2*(A_ELEMS + B_ELEMS)*sizeof(float);
    const int SMEM_DIFF  = 2*(2*A_ELEMS + B_ELEMS)*sizeof(float);
    static bool attr_set = false;
    if (!attr_set) {
        cudaFuncSetAttribute(tf32gemm<false>, cudaFuncAttributeMaxDynamicSharedMemorySize, SMEM_PLAIN);
        cudaFuncSetAttribute(tf32gemm<true>,  cudaFuncAttributeMaxDynamicSharedMemorySize, SMEM_DIFF);
        cudaFuncSetAttribute(tf32gemm_attn,   cudaFuncAttributeMaxDynamicSharedMemorySize, SMEM_PLAIN);
        attr_set = true;
    }

    const int Tts[3] = {1024, 512, 256};
    const int Tqs[3] = {512, 256, 128};
    const int ks [3] = {16, 32, 64};

    const float* tok_src  = tokens;
    const float* cent_src = centers;
    float* cent_dsts[3] = {cent_a, cent_b, cent_a};

    for (int i = 0; i < 3; i++) {
        int Tt = Tts[i], Tq = Tqs[i], k = ks[i];
        int Mq = BQN*Tq, Mt = BQN*Tt, Mr = Mq*k;
        float* cent_dst = cent_dsts[i];

        fps_kernel   <<<BQN, 256>>>(cent_src, Tt, Tq, rep);
        gather_kernel<<<Mq, 256>>>(tok_src, cent_src, rep, tok_q, skip, cent_dst, Tt, Tq);
        knn_kernel   <<<Mq, 256>>>(cent_dst, cent_src, Tt, Tq, k, nn);

        const float* tok_t_cur = tok_src;
        if (i > 0) {
            bn_partial <<<64, 256>>>(tok_q, Mq, tok_src, Mt, psum, psq);
            bn_finalize<<<1, 256>>>(psum, psq, 64, Mq + Mt, stats);
            int nq = Mq*CD, nt = Mt*CD;
            bn_apply<<<(nq+255)/256, 256>>>(tok_q, tok_q, nq, stats, bn1_g + i*CD, bn1_b + i*CD);
            bn_apply<<<(nt+255)/256, 256>>>(tok_src, tok_buf, nt, stats, bn1_g + i*CD, bn1_b + i*CD);
            tok_t_cur = tok_buf;
        }

        tf32gemm<false><<<dim3(CD/TBN, Mq/TBM), 256, SMEM_PLAIN>>>(Mq, CD, CD, tok_q,
            nullptr, nullptr, nullptr, 0, 0, 0,
            wq + (size_t)i*CD*CD, nullptr, nullptr, Qb, 0);
        tf32gemm<false><<<dim3(2*CD/TBN, Mt/TBM), 256, SMEM_PLAIN>>>(Mt, 2*CD, CD, tok_t_cur,
            nullptr, nullptr, nullptr, 0, 0, 0,
            wkv + (size_t)i*CD*2*CD, nullptr, nullptr, KV, 0);
        tf32gemm<true><<<dim3(CD/TBN, Mr/TBM), 256, SMEM_DIFF>>>(Mr, CD, CD, nullptr,
            Qb, KV, nn, Tq, k, Tt,
            att_w1 + (size_t)i*CD*CD, att_b1 + i*CD, nullptr, hidb, 1);
        // GEMM2 + softmax + V + skip fused
        tf32gemm_attn<<<dim3(CD/TBN, Mr/TBM), 256, SMEM_PLAIN>>>(Mr, CD, CD, hidb,
            att_w2 + (size_t)i*CD*CD, att_b2 + i*CD,
            KV, nn, Tq, k, Tt, skip, tq);

        bn_partial <<<64, 256>>>(tq, Mq, nullptr, 0, psum, psq);
        bn_finalize<<<1, 256>>>(psum, psq, 64, Mq, stats);
        int n2 = Mq*CD;
        bn_apply<<<(n2+255)/256, 256>>>(tq, tqbn, n2, stats, bn2_g + i*CD, bn2_b + i*CD);

        tf32gemm<false><<<dim3(2*CD/TBN, Mq/TBM), 256, SMEM_PLAIN>>>(Mq, 2*CD, CD, tqbn,
            nullptr, nullptr, nullptr, 0, 0, 0,
            mlp_w1 + (size_t)i*CD*2*CD, mlp_b1 + i*2*CD, nullptr, mlph, 1);
        tf32gemm<false><<<dim3(CD/TBN, Mq/TBM), 256, SMEM_PLAIN>>>(Mq, CD, 2*CD, mlph,
            nullptr, nullptr, nullptr, 0, 0, 0,
            mlp_w2 + (size_t)i*2*CD*CD, mlp_b2 + i*CD, tq, tok_buf, 0);

        tok_src  = tok_buf;
        cent_src = cent_dst;
    }

    pool_kernel     <<<BQN, 256>>>(tok_buf, pool, 128);
    emb_kernel      <<<BQN, 512>>>(pool, emb_w, emb_b, embv);
    final_bn_kernel <<<1, 512>>>(embv, embn_g, embn_b);
    topk_norm_kernel<<<BQN, 512>>>(embv, (float*)d_out);
}